// round 2
// baseline (speedup 1.0000x reference)
#include <cuda_runtime.h>
#include <math.h>

// ---------------- scratch (device globals; no allocation allowed) -----------
__device__ float g_x2[512 * 512];
__device__ float g_q[512 * 512];
__device__ float g_k[512 * 512];
__device__ float g_v[512 * 512];
__device__ float g_concat[512 * 512];
__device__ float g_y[512 * 512];
__device__ float g_y2[512 * 512];
__device__ float g_h[512 * 2048];

// ---------------- LayerNorm (ddof=1, eps added to sd) -----------------------
__global__ __launch_bounds__(256) void ln_kernel(
    const float* __restrict__ x, const float* __restrict__ alpha,
    const float* __restrict__ beta, float* __restrict__ out) {
    int row = blockIdx.x;
    int t = threadIdx.x;  // 256 threads, 2 elems each
    float2 v = ((const float2*)(x + (size_t)row * 512))[t];
    float s = v.x + v.y;
    float q = v.x * v.x + v.y * v.y;
    __shared__ float ssum[8], ssq[8];
#pragma unroll
    for (int off = 16; off; off >>= 1) {
        s += __shfl_xor_sync(~0u, s, off);
        q += __shfl_xor_sync(~0u, q, off);
    }
    int w = t >> 5, l = t & 31;
    if (l == 0) { ssum[w] = s; ssq[w] = q; }
    __syncthreads();
    float tot = 0.f, totq = 0.f;
#pragma unroll
    for (int i = 0; i < 8; i++) { tot += ssum[i]; totq += ssq[i]; }
    float mu  = tot * (1.0f / 512.0f);
    float var = (totq - 512.0f * mu * mu) * (1.0f / 511.0f);
    float inv = 1.0f / (sqrtf(var) + 1e-6f);
    float2 a  = ((const float2*)alpha)[t];
    float2 bb = ((const float2*)beta)[t];
    float2 o;
    o.x = a.x * (v.x - mu) * inv + bb.x;
    o.y = a.y * (v.y - mu) * inv + bb.y;
    ((float2*)(out + (size_t)row * 512))[t] = o;
}

// ---------------- fp32 tiled GEMM: C[M,N] = A[M,K] @ B[N,K]^T ---------------
// epilogue: + bias[n]; optional relu; optional + Res[m,n]
__global__ __launch_bounds__(256) void gemm_kernel(
    const float* __restrict__ A, const float* __restrict__ B,
    const float* __restrict__ bias, const float* __restrict__ Res,
    float* __restrict__ C, int M, int N, int K, int relu) {
    __shared__ float As[16][68];  // [k][m], 68 keeps float4 alignment + reduces conflicts
    __shared__ float Bs[16][68];  // [k][n]
    int tid = threadIdx.x;
    int m0 = blockIdx.y * 64, n0 = blockIdx.x * 64;
    int r = tid >> 2, qd = tid & 3;  // r: 0..63 row-in-tile, qd: which float4 of 16 k's
    const float* Ald = A + (size_t)(m0 + r) * K + qd * 4;
    const float* Bld = B + (size_t)(n0 + r) * K + qd * 4;
    int tx = tid & 15, ty = tid >> 4;  // tx -> n micro, ty -> m micro
    float acc[4][4] = {};
    for (int k0 = 0; k0 < K; k0 += 16) {
        float4 av = *(const float4*)(Ald + k0);
        float4 bv = *(const float4*)(Bld + k0);
        As[qd * 4 + 0][r] = av.x; As[qd * 4 + 1][r] = av.y;
        As[qd * 4 + 2][r] = av.z; As[qd * 4 + 3][r] = av.w;
        Bs[qd * 4 + 0][r] = bv.x; Bs[qd * 4 + 1][r] = bv.y;
        Bs[qd * 4 + 2][r] = bv.z; Bs[qd * 4 + 3][r] = bv.w;
        __syncthreads();
#pragma unroll
        for (int kk = 0; kk < 16; kk++) {
            float4 a = *(const float4*)&As[kk][ty * 4];
            float4 b = *(const float4*)&Bs[kk][tx * 4];
            acc[0][0] += a.x * b.x; acc[0][1] += a.x * b.y; acc[0][2] += a.x * b.z; acc[0][3] += a.x * b.w;
            acc[1][0] += a.y * b.x; acc[1][1] += a.y * b.y; acc[1][2] += a.y * b.z; acc[1][3] += a.y * b.w;
            acc[2][0] += a.z * b.x; acc[2][1] += a.z * b.y; acc[2][2] += a.z * b.z; acc[2][3] += a.z * b.w;
            acc[3][0] += a.w * b.x; acc[3][1] += a.w * b.y; acc[3][2] += a.w * b.z; acc[3][3] += a.w * b.w;
        }
        __syncthreads();
    }
    int mm = m0 + ty * 4, nn = n0 + tx * 4;
    float4 bz = *(const float4*)(bias + nn);
#pragma unroll
    for (int i = 0; i < 4; i++) {
        float4 c;
        c.x = acc[i][0] + bz.x; c.y = acc[i][1] + bz.y;
        c.z = acc[i][2] + bz.z; c.w = acc[i][3] + bz.w;
        if (relu) {
            c.x = fmaxf(c.x, 0.f); c.y = fmaxf(c.y, 0.f);
            c.z = fmaxf(c.z, 0.f); c.w = fmaxf(c.w, 0.f);
        }
        if (Res) {
            float4 rr = *(const float4*)(Res + (size_t)(mm + i) * N + nn);
            c.x += rr.x; c.y += rr.y; c.z += rr.z; c.w += rr.w;
        }
        *(float4*)(C + (size_t)(mm + i) * N + nn) = c;
    }
}

// ---------------- fused attention with connection biases --------------------
// One block per (b,i). Warp = head. lane covers dims {2l, 2l+1} of its head.
// score[b,h,i,j] = q . (k_j + cbk[b,j,i,h,:]) / 8  (+ mask bias)
// out[b,h,i,:]   = softmax_j(score) . (v_j + cbv[b,j,i,h,:])
__global__ __launch_bounds__(256) void attn_kernel(
    const float* __restrict__ cbk, const float* __restrict__ cbv,
    const int* __restrict__ mask) {
    int bi = blockIdx.x;             // 0..511
    int b = bi >> 8, i = bi & 255;
    int w = threadIdx.x >> 5;        // head 0..7
    int lane = threadIdx.x & 31;

    __shared__ float mb[256];
    mb[threadIdx.x] = (mask[(b << 8) + threadIdx.x] == 1) ? -1e9f : 0.0f;
    __syncthreads();

    int d0 = (w << 6) + (lane << 1);
    const float2 q2 = *(const float2*)(g_q + ((size_t)bi << 9) + d0);
    const float* kp  = g_k + ((size_t)(b << 8) << 9) + d0;    // + j*512
    const float* vp  = g_v + ((size_t)(b << 8) << 9) + d0;
    // cbk index: ((b*256 + j)*256 + i)*512 + d
    const size_t cb_base = ((size_t)b * 256 * 256 + i) * 512 + d0;
    const float* ckp = cbk + cb_base;                          // + j*131072
    const float* cvp = cbv + cb_base;

    float m = -INFINITY, l = 0.0f;
    float2 acc = make_float2(0.f, 0.f);

    for (int j0 = 0; j0 < 256; j0 += 4) {
        float2 kc[4], vc[4];
#pragma unroll
        for (int u = 0; u < 4; u++) {
            size_t j = (size_t)(j0 + u);
            float2 kk = *(const float2*)(kp + j * 512);
            float2 ck = *(const float2*)(ckp + j * 131072);
            float2 vv = *(const float2*)(vp + j * 512);
            float2 cv = *(const float2*)(cvp + j * 131072);
            kc[u] = make_float2(kk.x + ck.x, kk.y + ck.y);
            vc[u] = make_float2(vv.x + cv.x, vv.y + cv.y);
        }
        float s[4];
#pragma unroll
        for (int u = 0; u < 4; u++) s[u] = q2.x * kc[u].x + q2.y * kc[u].y;
#pragma unroll
        for (int off = 16; off; off >>= 1) {
#pragma unroll
            for (int u = 0; u < 4; u++) s[u] += __shfl_xor_sync(~0u, s[u], off);
        }
#pragma unroll
        for (int u = 0; u < 4; u++) s[u] = s[u] * 0.125f + mb[j0 + u];

        float mc = fmaxf(fmaxf(s[0], s[1]), fmaxf(s[2], s[3]));
        float mn = fmaxf(m, mc);
        float corr = __expf(m - mn);   // m starts at -inf -> corr = 0 first time
        float ps = 0.f, ax = 0.f, ay = 0.f;
#pragma unroll
        for (int u = 0; u < 4; u++) {
            float p = __expf(s[u] - mn);
            ps += p;
            ax += p * vc[u].x;
            ay += p * vc[u].y;
        }
        l = l * corr + ps;
        acc.x = acc.x * corr + ax;
        acc.y = acc.y * corr + ay;
        m = mn;
    }
    float invl = 1.0f / l;
    *(float2*)(g_concat + ((size_t)bi << 9) + d0) =
        make_float2(acc.x * invl, acc.y * invl);
}

// ---------------- launch ----------------------------------------------------
extern "C" void kernel_launch(void* const* d_in, const int* in_sizes, int n_in,
                              void* d_out, int out_size) {
    const float* x    = (const float*)d_in[0];
    const float* cbk  = (const float*)d_in[1];
    const float* cbv  = (const float*)d_in[2];
    const int*   mask = (const int*)d_in[3];
    const float* Wq = (const float*)d_in[4];
    const float* bq = (const float*)d_in[5];
    const float* Wk = (const float*)d_in[6];
    const float* bk = (const float*)d_in[7];
    const float* Wv = (const float*)d_in[8];
    const float* bv = (const float*)d_in[9];
    const float* Wo = (const float*)d_in[10];
    const float* bo = (const float*)d_in[11];
    const float* alpha1 = (const float*)d_in[12];
    const float* beta1  = (const float*)d_in[13];
    const float* alpha2 = (const float*)d_in[14];
    const float* beta2  = (const float*)d_in[15];
    const float* W1 = (const float*)d_in[16];
    const float* b1 = (const float*)d_in[17];
    const float* W2 = (const float*)d_in[18];
    const float* b2 = (const float*)d_in[19];
    float* out = (float*)d_out;

    float *px2, *pq, *pk, *pv, *pcc, *py, *py2, *ph;
    cudaGetSymbolAddress((void**)&px2, g_x2);
    cudaGetSymbolAddress((void**)&pq,  g_q);
    cudaGetSymbolAddress((void**)&pk,  g_k);
    cudaGetSymbolAddress((void**)&pv,  g_v);
    cudaGetSymbolAddress((void**)&pcc, g_concat);
    cudaGetSymbolAddress((void**)&py,  g_y);
    cudaGetSymbolAddress((void**)&py2, g_y2);
    cudaGetSymbolAddress((void**)&ph,  g_h);

    // 1) LN1
    ln_kernel<<<512, 256>>>(x, alpha1, beta1, px2);
    // 2-4) Q,K,V projections (512x512 @ 512x512^T)
    gemm_kernel<<<dim3(8, 8), 256>>>(px2, Wq, bq, nullptr, pq, 512, 512, 512, 0);
    gemm_kernel<<<dim3(8, 8), 256>>>(px2, Wk, bk, nullptr, pk, 512, 512, 512, 0);
    gemm_kernel<<<dim3(8, 8), 256>>>(px2, Wv, bv, nullptr, pv, 512, 512, 512, 0);
    // 5) fused attention (streams both 256MB bias tensors once)
    attn_kernel<<<512, 256>>>(cbk, cbv, mask);
    // 6) output projection + residual(x)
    gemm_kernel<<<dim3(8, 8), 256>>>(pcc, Wo, bo, x, py, 512, 512, 512, 0);
    // 7) LN2
    ln_kernel<<<512, 256>>>(py, alpha2, beta2, py2);
    // 8) FFN up + ReLU (512x2048)
    gemm_kernel<<<dim3(32, 8), 256>>>(py2, W1, b1, nullptr, ph, 512, 2048, 512, 1);
    // 9) FFN down + residual(y) -> final output
    gemm_kernel<<<dim3(8, 8), 256>>>(ph, W2, b2, py, out, 512, 512, 2048, 0);
}

// round 3
// speedup vs baseline: 1.0773x; 1.0773x over previous
#include <cuda_runtime.h>
#include <math.h>

// ---------------- scratch (device globals; no allocation allowed) -----------
__device__ float g_x2[512 * 512];
__device__ float g_q[512 * 512];
__device__ float g_k[512 * 512];
__device__ float g_v[512 * 512];
__device__ float g_concat[512 * 512];
__device__ float g_y[512 * 512];
__device__ float g_y2[512 * 512];
__device__ float g_h[512 * 2048];

// ---------------- helpers ----------------------------------------------------
__device__ __forceinline__ unsigned f2tf(float x) {
    unsigned r;
    asm("cvt.rna.tf32.f32 %0, %1;" : "=r"(r) : "f"(x));
    return r;
}

__device__ __forceinline__ void mma_tf32(float c[4],
                                         unsigned a0, unsigned a1, unsigned a2, unsigned a3,
                                         unsigned b0, unsigned b1) {
    asm volatile(
        "mma.sync.aligned.m16n8k8.row.col.f32.tf32.tf32.f32 "
        "{%0,%1,%2,%3}, {%4,%5,%6,%7}, {%8,%9}, {%0,%1,%2,%3};"
        : "+f"(c[0]), "+f"(c[1]), "+f"(c[2]), "+f"(c[3])
        : "r"(a0), "r"(a1), "r"(a2), "r"(a3), "r"(b0), "r"(b1));
}

// ---------------- LayerNorm (ddof=1, eps added to sd) -----------------------
__global__ __launch_bounds__(256) void ln_kernel(
    const float* __restrict__ x, const float* __restrict__ alpha,
    const float* __restrict__ beta, float* __restrict__ out) {
    int row = blockIdx.x;
    int t = threadIdx.x;
    float2 v = ((const float2*)(x + (size_t)row * 512))[t];
    float s = v.x + v.y;
    float q = v.x * v.x + v.y * v.y;
    __shared__ float ssum[8], ssq[8];
#pragma unroll
    for (int off = 16; off; off >>= 1) {
        s += __shfl_xor_sync(~0u, s, off);
        q += __shfl_xor_sync(~0u, q, off);
    }
    int w = t >> 5, l = t & 31;
    if (l == 0) { ssum[w] = s; ssq[w] = q; }
    __syncthreads();
    float tot = 0.f, totq = 0.f;
#pragma unroll
    for (int i = 0; i < 8; i++) { tot += ssum[i]; totq += ssq[i]; }
    float mu  = tot * (1.0f / 512.0f);
    float var = (totq - 512.0f * mu * mu) * (1.0f / 511.0f);
    float inv = 1.0f / (sqrtf(var) + 1e-6f);
    float2 a  = ((const float2*)alpha)[t];
    float2 bb = ((const float2*)beta)[t];
    float2 o;
    o.x = a.x * (v.x - mu) * inv + bb.x;
    o.y = a.y * (v.y - mu) * inv + bb.y;
    ((float2*)(out + (size_t)row * 512))[t] = o;
}

// ---------------- 3xTF32 tensor-core GEMM: C[M,N] = A[M,K] @ B[N,K]^T -------
// Block tile 64x64, BK=32, 8 warps (warp grid 2x4, warp tile 32x16).
// epilogue: + bias[n]; optional relu; optional + Res[m,n]
__device__ __forceinline__ void gemm_body(
    const float* __restrict__ A, const float* __restrict__ B,
    const float* __restrict__ bias, const float* __restrict__ Res,
    float* __restrict__ C, int M, int N, int K, int relu) {
    // stride 36: fragment LDS bank = (4*row + col) % 32 -> injective, conflict-free
    __shared__ float AsB[64][36], AsS[64][36], BsB[64][36], BsS[64][36];
    int tid = threadIdx.x;
    int m0 = blockIdx.y * 64, n0 = blockIdx.x * 64;
    int lr = tid >> 2;          // 0..63 tile row for loading
    int lc = (tid & 3) * 8;     // 8 consecutive k-floats
    const float* Ald = A + (size_t)(m0 + lr) * K + lc;
    const float* Bld = B + (size_t)(n0 + lr) * K + lc;

    int warp = tid >> 5, lane = tid & 31;
    int wm = warp >> 2, wn = warp & 3;  // warp tile origin: (wm*32, wn*16)
    int g = lane >> 2, tg = lane & 3;   // mma groupID / threadID_in_group

    float acc[2][2][4];
#pragma unroll
    for (int i = 0; i < 2; i++)
#pragma unroll
        for (int j = 0; j < 2; j++)
#pragma unroll
            for (int r = 0; r < 4; r++) acc[i][j][r] = 0.f;

    for (int k0 = 0; k0 < K; k0 += 32) {
        float4 av0 = *(const float4*)(Ald + k0);
        float4 av1 = *(const float4*)(Ald + k0 + 4);
        float4 bv0 = *(const float4*)(Bld + k0);
        float4 bv1 = *(const float4*)(Bld + k0 + 4);
        __syncthreads();  // previous chunk fully consumed
        const float* ap = (const float*)&av0;
        const float* bp = (const float*)&bv0;
#pragma unroll
        for (int i = 0; i < 8; i++) {
            float va = ap[i];  // av0/av1 contiguous on stack via union trick below
            float vb = bp[i];
            // (rely on layout: place av1/bv1 right after) -- do explicitly instead:
            if (i >= 4) { va = ((const float*)&av1)[i - 4]; vb = ((const float*)&bv1)[i - 4]; }
            float abf = __uint_as_float(f2tf(va));
            AsB[lr][lc + i] = abf;
            AsS[lr][lc + i] = __uint_as_float(f2tf(va - abf));
            float bbf = __uint_as_float(f2tf(vb));
            BsB[lr][lc + i] = bbf;
            BsS[lr][lc + i] = __uint_as_float(f2tf(vb - bbf));
        }
        __syncthreads();
#pragma unroll
        for (int kk = 0; kk < 32; kk += 8) {
            unsigned aB[2][4], aS[2][4], bB[2][2], bS[2][2];
#pragma unroll
            for (int mt = 0; mt < 2; mt++) {
                int r0 = wm * 32 + mt * 16 + g;
                aB[mt][0] = __float_as_uint(AsB[r0][kk + tg]);
                aB[mt][1] = __float_as_uint(AsB[r0 + 8][kk + tg]);
                aB[mt][2] = __float_as_uint(AsB[r0][kk + tg + 4]);
                aB[mt][3] = __float_as_uint(AsB[r0 + 8][kk + tg + 4]);
                aS[mt][0] = __float_as_uint(AsS[r0][kk + tg]);
                aS[mt][1] = __float_as_uint(AsS[r0 + 8][kk + tg]);
                aS[mt][2] = __float_as_uint(AsS[r0][kk + tg + 4]);
                aS[mt][3] = __float_as_uint(AsS[r0 + 8][kk + tg + 4]);
            }
#pragma unroll
            for (int nt = 0; nt < 2; nt++) {
                int c0 = wn * 16 + nt * 8 + g;
                bB[nt][0] = __float_as_uint(BsB[c0][kk + tg]);
                bB[nt][1] = __float_as_uint(BsB[c0][kk + tg + 4]);
                bS[nt][0] = __float_as_uint(BsS[c0][kk + tg]);
                bS[nt][1] = __float_as_uint(BsS[c0][kk + tg + 4]);
            }
#pragma unroll
            for (int mt = 0; mt < 2; mt++)
#pragma unroll
                for (int nt = 0; nt < 2; nt++) {
                    mma_tf32(acc[mt][nt], aB[mt][0], aB[mt][1], aB[mt][2], aB[mt][3],
                             bB[nt][0], bB[nt][1]);
                    mma_tf32(acc[mt][nt], aB[mt][0], aB[mt][1], aB[mt][2], aB[mt][3],
                             bS[nt][0], bS[nt][1]);
                    mma_tf32(acc[mt][nt], aS[mt][0], aS[mt][1], aS[mt][2], aS[mt][3],
                             bB[nt][0], bB[nt][1]);
                }
        }
    }
    // epilogue
#pragma unroll
    for (int mt = 0; mt < 2; mt++)
#pragma unroll
        for (int nt = 0; nt < 2; nt++) {
            int row = m0 + wm * 32 + mt * 16 + g;
            int col = n0 + wn * 16 + nt * 8 + tg * 2;
            float2 bz = *(const float2*)(bias + col);
#pragma unroll
            for (int h = 0; h < 2; h++) {
                int rr = row + h * 8;
                float cx = acc[mt][nt][h * 2 + 0] + bz.x;
                float cy = acc[mt][nt][h * 2 + 1] + bz.y;
                if (relu) { cx = fmaxf(cx, 0.f); cy = fmaxf(cy, 0.f); }
                if (Res) {
                    float2 rv = *(const float2*)(Res + (size_t)rr * N + col);
                    cx += rv.x; cy += rv.y;
                }
                *(float2*)(C + (size_t)rr * N + col) = make_float2(cx, cy);
            }
        }
}

__global__ __launch_bounds__(256) void gemm_tf32_kernel(
    const float* __restrict__ A, const float* __restrict__ B,
    const float* __restrict__ bias, const float* __restrict__ Res,
    float* __restrict__ C, int M, int N, int K, int relu) {
    gemm_body(A, B, bias, Res, C, M, N, K, relu);
}

// fused QKV: blockIdx.z selects which projection
__global__ __launch_bounds__(256) void gemm_qkv_kernel(
    const float* __restrict__ A,
    const float* __restrict__ Wq, const float* __restrict__ bq, float* __restrict__ Q,
    const float* __restrict__ Wk, const float* __restrict__ bk, float* __restrict__ Kp,
    const float* __restrict__ Wv, const float* __restrict__ bv, float* __restrict__ V) {
    const float* B; const float* bias; float* C;
    if (blockIdx.z == 0)      { B = Wq; bias = bq; C = Q; }
    else if (blockIdx.z == 1) { B = Wk; bias = bk; C = Kp; }
    else                      { B = Wv; bias = bv; C = V; }
    gemm_body(A, B, bias, nullptr, C, 512, 512, 512, 0);
}

// ---------------- fused attention with connection biases --------------------
__global__ __launch_bounds__(256) void attn_kernel(
    const float* __restrict__ cbk, const float* __restrict__ cbv,
    const int* __restrict__ mask) {
    int bi = blockIdx.x;             // 0..511
    int b = bi >> 8, i = bi & 255;
    int w = threadIdx.x >> 5;        // head 0..7
    int lane = threadIdx.x & 31;

    __shared__ float mb[256];
    mb[threadIdx.x] = (mask[(b << 8) + threadIdx.x] == 1) ? -1e9f : 0.0f;
    __syncthreads();

    int d0 = (w << 6) + (lane << 1);
    const float2 q2 = *(const float2*)(g_q + ((size_t)bi << 9) + d0);
    const float* kp  = g_k + ((size_t)(b << 8) << 9) + d0;
    const float* vp  = g_v + ((size_t)(b << 8) << 9) + d0;
    const size_t cb_base = ((size_t)b * 256 * 256 + i) * 512 + d0;
    const float* ckp = cbk + cb_base;
    const float* cvp = cbv + cb_base;

    float m = -INFINITY, l = 0.0f;
    float2 acc = make_float2(0.f, 0.f);

    for (int j0 = 0; j0 < 256; j0 += 4) {
        float2 kc[4], vc[4];
#pragma unroll
        for (int u = 0; u < 4; u++) {
            size_t j = (size_t)(j0 + u);
            float2 kk = *(const float2*)(kp + j * 512);
            float2 ck = *(const float2*)(ckp + j * 131072);
            float2 vv = *(const float2*)(vp + j * 512);
            float2 cv = *(const float2*)(cvp + j * 131072);
            kc[u] = make_float2(kk.x + ck.x, kk.y + ck.y);
            vc[u] = make_float2(vv.x + cv.x, vv.y + cv.y);
        }
        float s[4];
#pragma unroll
        for (int u = 0; u < 4; u++) s[u] = q2.x * kc[u].x + q2.y * kc[u].y;
#pragma unroll
        for (int off = 16; off; off >>= 1) {
#pragma unroll
            for (int u = 0; u < 4; u++) s[u] += __shfl_xor_sync(~0u, s[u], off);
        }
#pragma unroll
        for (int u = 0; u < 4; u++) s[u] = s[u] * 0.125f + mb[j0 + u];

        float mc = fmaxf(fmaxf(s[0], s[1]), fmaxf(s[2], s[3]));
        float mn = fmaxf(m, mc);
        float corr = __expf(m - mn);
        float ps = 0.f, ax = 0.f, ay = 0.f;
#pragma unroll
        for (int u = 0; u < 4; u++) {
            float p = __expf(s[u] - mn);
            ps += p;
            ax += p * vc[u].x;
            ay += p * vc[u].y;
        }
        l = l * corr + ps;
        acc.x = acc.x * corr + ax;
        acc.y = acc.y * corr + ay;
        m = mn;
    }
    float invl = 1.0f / l;
    *(float2*)(g_concat + ((size_t)bi << 9) + d0) =
        make_float2(acc.x * invl, acc.y * invl);
}

// ---------------- launch ----------------------------------------------------
extern "C" void kernel_launch(void* const* d_in, const int* in_sizes, int n_in,
                              void* d_out, int out_size) {
    const float* x    = (const float*)d_in[0];
    const float* cbk  = (const float*)d_in[1];
    const float* cbv  = (const float*)d_in[2];
    const int*   mask = (const int*)d_in[3];
    const float* Wq = (const float*)d_in[4];
    const float* bq = (const float*)d_in[5];
    const float* Wk = (const float*)d_in[6];
    const float* bk = (const float*)d_in[7];
    const float* Wv = (const float*)d_in[8];
    const float* bv = (const float*)d_in[9];
    const float* Wo = (const float*)d_in[10];
    const float* bo = (const float*)d_in[11];
    const float* alpha1 = (const float*)d_in[12];
    const float* beta1  = (const float*)d_in[13];
    const float* alpha2 = (const float*)d_in[14];
    const float* beta2  = (const float*)d_in[15];
    const float* W1 = (const float*)d_in[16];
    const float* b1 = (const float*)d_in[17];
    const float* W2 = (const float*)d_in[18];
    const float* b2 = (const float*)d_in[19];
    float* out = (float*)d_out;

    float *px2, *pq, *pk, *pv, *pcc, *py, *py2, *ph;
    cudaGetSymbolAddress((void**)&px2, g_x2);
    cudaGetSymbolAddress((void**)&pq,  g_q);
    cudaGetSymbolAddress((void**)&pk,  g_k);
    cudaGetSymbolAddress((void**)&pv,  g_v);
    cudaGetSymbolAddress((void**)&pcc, g_concat);
    cudaGetSymbolAddress((void**)&py,  g_y);
    cudaGetSymbolAddress((void**)&py2, g_y2);
    cudaGetSymbolAddress((void**)&ph,  g_h);

    // 1) LN1
    ln_kernel<<<512, 256>>>(x, alpha1, beta1, px2);
    // 2) fused Q,K,V projections (tensor cores, grid 8x8x3 = 192 blocks)
    gemm_qkv_kernel<<<dim3(8, 8, 3), 256>>>(px2, Wq, bq, pq, Wk, bk, pk, Wv, bv, pv);
    // 3) fused attention (streams both 256MB bias tensors once)
    attn_kernel<<<512, 256>>>(cbk, cbv, mask);
    // 4) output projection + residual(x)
    gemm_tf32_kernel<<<dim3(8, 8), 256>>>(pcc, Wo, bo, x, py, 512, 512, 512, 0);
    // 5) LN2
    ln_kernel<<<512, 256>>>(py, alpha2, beta2, py2);
    // 6) FFN up + ReLU
    gemm_tf32_kernel<<<dim3(32, 8), 256>>>(py2, W1, b1, nullptr, ph, 512, 2048, 512, 1);
    // 7) FFN down + residual(y) -> final output
    gemm_tf32_kernel<<<dim3(8, 8), 256>>>(ph, W2, b2, py, out, 512, 512, 2048, 0);
}

// round 5
// speedup vs baseline: 1.4897x; 1.3828x over previous
#include <cuda_runtime.h>
#include <math.h>

#define SEQ 512   // b*s rows
#define DM  512
#define DF  2048

// ---------------- scratch (device globals; no allocation allowed) -----------
__device__ float g_x2B[SEQ*DM], g_x2S[SEQ*DM];
__device__ float g_q[SEQ*DM], g_k[SEQ*DM], g_v[SEQ*DM];
__device__ float g_ccB[SEQ*DM], g_ccS[SEQ*DM];
__device__ float g_y[SEQ*DM];
__device__ float g_y2B[SEQ*DM], g_y2S[SEQ*DM];
__device__ float g_hB[SEQ*DF], g_hS[SEQ*DF];
__device__ float g_WqB[DM*DM], g_WqS[DM*DM];
__device__ float g_WkB[DM*DM], g_WkS[DM*DM];
__device__ float g_WvB[DM*DM], g_WvS[DM*DM];
__device__ float g_WoB[DM*DM], g_WoS[DM*DM];
__device__ float g_W1B[DF*DM], g_W1S[DF*DM];
__device__ float g_W2B[DM*DF], g_W2S[DM*DF];

// ---------------- helpers ----------------------------------------------------
__device__ __forceinline__ float tf32r(float x) {
    unsigned r;
    asm("cvt.rna.tf32.f32 %0, %1;" : "=r"(r) : "f"(x));
    return __uint_as_float(r);
}

__device__ __forceinline__ void mma_tf32(float c[4],
                                         unsigned a0, unsigned a1, unsigned a2, unsigned a3,
                                         unsigned b0, unsigned b1) {
    asm volatile(
        "mma.sync.aligned.m16n8k8.row.col.f32.tf32.tf32.f32 "
        "{%0,%1,%2,%3}, {%4,%5,%6,%7}, {%8,%9}, {%0,%1,%2,%3};"
        : "+f"(c[0]), "+f"(c[1]), "+f"(c[2]), "+f"(c[3])
        : "r"(a0), "r"(a1), "r"(a2), "r"(a3), "r"(b0), "r"(b1));
}

// ---------------- weight splitting (big/small tf32 planes) -------------------
__global__ __launch_bounds__(256) void split_weights_kernel(
    const float* __restrict__ Wq, const float* __restrict__ Wk,
    const float* __restrict__ Wv, const float* __restrict__ Wo,
    const float* __restrict__ W1, const float* __restrict__ W2) {
    int i = blockIdx.x * 256 + threadIdx.x;     // float4 index, total 786432
    const int S = 65536, L = 262144;            // float4 counts
    const float* src; float* dB; float* dS; int o;
    if (i < 4 * S) {
        int w = i / S; o = i - w * S;
        src = (w == 0) ? Wq : (w == 1) ? Wk : (w == 2) ? Wv : Wo;
        dB  = (w == 0) ? g_WqB : (w == 1) ? g_WkB : (w == 2) ? g_WvB : g_WoB;
        dS  = (w == 0) ? g_WqS : (w == 1) ? g_WkS : (w == 2) ? g_WvS : g_WoS;
    } else if (i < 4 * S + L) {
        o = i - 4 * S; src = W1; dB = g_W1B; dS = g_W1S;
    } else {
        o = i - 4 * S - L; src = W2; dB = g_W2B; dS = g_W2S;
    }
    float4 v = ((const float4*)src)[o];
    float4 b, s;
    b.x = tf32r(v.x); s.x = tf32r(v.x - b.x);
    b.y = tf32r(v.y); s.y = tf32r(v.y - b.y);
    b.z = tf32r(v.z); s.z = tf32r(v.z - b.z);
    b.w = tf32r(v.w); s.w = tf32r(v.w - b.w);
    ((float4*)dB)[o] = b;
    ((float4*)dS)[o] = s;
}

// ---------------- LayerNorm (ddof=1) with split output -----------------------
__global__ __launch_bounds__(256) void ln_split_kernel(
    const float* __restrict__ x, const float* __restrict__ alpha,
    const float* __restrict__ beta, float* __restrict__ outB,
    float* __restrict__ outS) {
    int row = blockIdx.x;
    int t = threadIdx.x;
    float2 v = ((const float2*)(x + (size_t)row * 512))[t];
    float s = v.x + v.y;
    float q = v.x * v.x + v.y * v.y;
    __shared__ float ssum[8], ssq[8];
#pragma unroll
    for (int off = 16; off; off >>= 1) {
        s += __shfl_xor_sync(~0u, s, off);
        q += __shfl_xor_sync(~0u, q, off);
    }
    int w = t >> 5, l = t & 31;
    if (l == 0) { ssum[w] = s; ssq[w] = q; }
    __syncthreads();
    float tot = 0.f, totq = 0.f;
#pragma unroll
    for (int i = 0; i < 8; i++) { tot += ssum[i]; totq += ssq[i]; }
    float mu  = tot * (1.0f / 512.0f);
    float var = (totq - 512.0f * mu * mu) * (1.0f / 511.0f);
    float inv = 1.0f / (sqrtf(var) + 1e-6f);
    float2 a  = ((const float2*)alpha)[t];
    float2 bb = ((const float2*)beta)[t];
    float ox = a.x * (v.x - mu) * inv + bb.x;
    float oy = a.y * (v.y - mu) * inv + bb.y;
    float bx = tf32r(ox), by = tf32r(oy);
    ((float2*)(outB + (size_t)row * 512))[t] = make_float2(bx, by);
    ((float2*)(outS + (size_t)row * 512))[t] = make_float2(ox - bx, oy - by);
}

// ---------------- 3xTF32 GEMM on pre-split planes ---------------------------
// C[M,N] = A[M,K] @ B[N,K]^T. CTA tile 32x64, BK=32, 128 threads (4 warps,
// warp tile 32x16). Register double-buffered gmem loads.
// Output: plain C (+bias, +Res, relu) and/or split planes CB/CS.
__device__ __forceinline__ void gemm_body(
    const float* __restrict__ AB, const float* __restrict__ AS,
    const float* __restrict__ BB, const float* __restrict__ BS,
    const float* __restrict__ bias, const float* __restrict__ Res,
    float* __restrict__ C, float* __restrict__ CB, float* __restrict__ CS,
    int N, int K, int relu) {
    __shared__ float sAB[32][36], sAS[32][36];
    __shared__ float sBB[64][36], sBS[64][36];
    int tid = threadIdx.x;
    int m0 = blockIdx.y * 32, n0 = blockIdx.x * 64;
    int ra = tid >> 2, ka = (tid & 3) * 8;    // A: 8 floats/row-chunk
    int rb = tid >> 1, kb = (tid & 1) * 16;   // B: 16 floats/row-chunk
    const float* pAB = AB + (size_t)(m0 + ra) * K + ka;
    const float* pAS = AS + (size_t)(m0 + ra) * K + ka;
    const float* pBB = BB + (size_t)(n0 + rb) * K + kb;
    const float* pBS = BS + (size_t)(n0 + rb) * K + kb;

    int w = tid >> 5, lane = tid & 31;
    int g = lane >> 2, tg = lane & 3;

    float acc[2][2][4] = {};

    float4 rAB[2], rAS[2], rBB[4], rBS[4];
    rAB[0] = *(const float4*)(pAB); rAB[1] = *(const float4*)(pAB + 4);
    rAS[0] = *(const float4*)(pAS); rAS[1] = *(const float4*)(pAS + 4);
#pragma unroll
    for (int i = 0; i < 4; i++) {
        rBB[i] = *(const float4*)(pBB + i * 4);
        rBS[i] = *(const float4*)(pBS + i * 4);
    }

    for (int k0 = 0; k0 < K; k0 += 32) {
        __syncthreads();   // previous stage fully consumed
#pragma unroll
        for (int i = 0; i < 8; i++) {
            sAB[ra][ka + i] = ((const float*)rAB)[i];
            sAS[ra][ka + i] = ((const float*)rAS)[i];
        }
#pragma unroll
        for (int i = 0; i < 16; i++) {
            sBB[rb][kb + i] = ((const float*)rBB)[i];
            sBS[rb][kb + i] = ((const float*)rBS)[i];
        }
        __syncthreads();
        if (k0 + 32 < K) {   // prefetch next stage (overlaps with MMAs below)
            pAB += 32; pAS += 32; pBB += 32; pBS += 32;
            rAB[0] = *(const float4*)(pAB); rAB[1] = *(const float4*)(pAB + 4);
            rAS[0] = *(const float4*)(pAS); rAS[1] = *(const float4*)(pAS + 4);
#pragma unroll
            for (int i = 0; i < 4; i++) {
                rBB[i] = *(const float4*)(pBB + i * 4);
                rBS[i] = *(const float4*)(pBS + i * 4);
            }
        }
#pragma unroll
        for (int kk = 0; kk < 32; kk += 8) {
            unsigned aB[2][4], aS[2][4], bB[2][2], bS[2][2];
#pragma unroll
            for (int mt = 0; mt < 2; mt++) {
                int r0 = mt * 16 + g;
                aB[mt][0] = __float_as_uint(sAB[r0][kk + tg]);
                aB[mt][1] = __float_as_uint(sAB[r0 + 8][kk + tg]);
                aB[mt][2] = __float_as_uint(sAB[r0][kk + tg + 4]);
                aB[mt][3] = __float_as_uint(sAB[r0 + 8][kk + tg + 4]);
                aS[mt][0] = __float_as_uint(sAS[r0][kk + tg]);
                aS[mt][1] = __float_as_uint(sAS[r0 + 8][kk + tg]);
                aS[mt][2] = __float_as_uint(sAS[r0][kk + tg + 4]);
                aS[mt][3] = __float_as_uint(sAS[r0 + 8][kk + tg + 4]);
            }
#pragma unroll
            for (int nt = 0; nt < 2; nt++) {
                int c0 = w * 16 + nt * 8 + g;
                bB[nt][0] = __float_as_uint(sBB[c0][kk + tg]);
                bB[nt][1] = __float_as_uint(sBB[c0][kk + tg + 4]);
                bS[nt][0] = __float_as_uint(sBS[c0][kk + tg]);
                bS[nt][1] = __float_as_uint(sBS[c0][kk + tg + 4]);
            }
#pragma unroll
            for (int mt = 0; mt < 2; mt++)
#pragma unroll
                for (int nt = 0; nt < 2; nt++) {
                    mma_tf32(acc[mt][nt], aB[mt][0], aB[mt][1], aB[mt][2], aB[mt][3],
                             bB[nt][0], bB[nt][1]);
                    mma_tf32(acc[mt][nt], aB[mt][0], aB[mt][1], aB[mt][2], aB[mt][3],
                             bS[nt][0], bS[nt][1]);
                    mma_tf32(acc[mt][nt], aS[mt][0], aS[mt][1], aS[mt][2], aS[mt][3],
                             bB[nt][0], bB[nt][1]);
                }
        }
    }
    // epilogue
#pragma unroll
    for (int mt = 0; mt < 2; mt++)
#pragma unroll
        for (int nt = 0; nt < 2; nt++) {
            int row = m0 + mt * 16 + g;
            int col = n0 + w * 16 + nt * 8 + tg * 2;
            float2 bz = *(const float2*)(bias + col);
#pragma unroll
            for (int h = 0; h < 2; h++) {
                int rr = row + h * 8;
                float cx = acc[mt][nt][h * 2 + 0] + bz.x;
                float cy = acc[mt][nt][h * 2 + 1] + bz.y;
                if (relu) { cx = fmaxf(cx, 0.f); cy = fmaxf(cy, 0.f); }
                if (Res) {
                    float2 rv = *(const float2*)(Res + (size_t)rr * N + col);
                    cx += rv.x; cy += rv.y;
                }
                if (C)
                    *(float2*)(C + (size_t)rr * N + col) = make_float2(cx, cy);
                if (CB) {
                    float bx = tf32r(cx), by = tf32r(cy);
                    *(float2*)(CB + (size_t)rr * N + col) = make_float2(bx, by);
                    *(float2*)(CS + (size_t)rr * N + col) =
                        make_float2(cx - bx, cy - by);
                }
            }
        }
}

// fused QKV: blockIdx.z selects projection. A = split x2, weights = split globals.
__global__ __launch_bounds__(128) void gemm_qkv_kernel(
    const float* __restrict__ bq, const float* __restrict__ bk,
    const float* __restrict__ bv) {
    const float *BB, *BS, *bias; float* C;
    if (blockIdx.z == 0)      { BB = g_WqB; BS = g_WqS; bias = bq; C = g_q; }
    else if (blockIdx.z == 1) { BB = g_WkB; BS = g_WkS; bias = bk; C = g_k; }
    else                      { BB = g_WvB; BS = g_WvS; bias = bv; C = g_v; }
    gemm_body(g_x2B, g_x2S, BB, BS, bias, nullptr, C, nullptr, nullptr,
              512, 512, 0);
}

__global__ __launch_bounds__(128) void gemm_wo_kernel(
    const float* __restrict__ bo, const float* __restrict__ x) {
    gemm_body(g_ccB, g_ccS, g_WoB, g_WoS, bo, x, g_y, nullptr, nullptr,
              512, 512, 0);
}

__global__ __launch_bounds__(128) void gemm_ffn1_kernel(
    const float* __restrict__ b1) {
    gemm_body(g_y2B, g_y2S, g_W1B, g_W1S, b1, nullptr, nullptr, g_hB, g_hS,
              2048, 512, 1);
}

__global__ __launch_bounds__(128) void gemm_ffn2_kernel(
    const float* __restrict__ b2, float* __restrict__ out) {
    gemm_body(g_hB, g_hS, g_W2B, g_W2S, b2, g_y, out, nullptr, nullptr,
              512, 2048, 0);
}

// ---------------- fused attention with connection biases --------------------
__global__ __launch_bounds__(256) void attn_kernel(
    const float* __restrict__ cbk, const float* __restrict__ cbv,
    const int* __restrict__ mask) {
    int bi = blockIdx.x;             // 0..511
    int b = bi >> 8, i = bi & 255;
    int w = threadIdx.x >> 5;        // head 0..7
    int lane = threadIdx.x & 31;

    __shared__ float mb[256];
    mb[threadIdx.x] = (mask[(b << 8) + threadIdx.x] == 1) ? -1e9f : 0.0f;
    __syncthreads();

    int d0 = (w << 6) + (lane << 1);
    const float2 q2 = *(const float2*)(g_q + ((size_t)bi << 9) + d0);
    const float* kp  = g_k + ((size_t)(b << 8) << 9) + d0;
    const float* vp  = g_v + ((size_t)(b << 8) << 9) + d0;
    const size_t cb_base = ((size_t)b * 256 * 256 + i) * 512 + d0;
    const float* ckp = cbk + cb_base;
    const float* cvp = cbv + cb_base;

    float m = -INFINITY, l = 0.0f;
    float2 acc = make_float2(0.f, 0.f);

    for (int j0 = 0; j0 < 256; j0 += 4) {
        float2 kc[4], vc[4];
#pragma unroll
        for (int u = 0; u < 4; u++) {
            size_t j = (size_t)(j0 + u);
            float2 kk = *(const float2*)(kp + j * 512);
            float2 ck = *(const float2*)(ckp + j * 131072);
            float2 vv = *(const float2*)(vp + j * 512);
            float2 cv = *(const float2*)(cvp + j * 131072);
            kc[u] = make_float2(kk.x + ck.x, kk.y + ck.y);
            vc[u] = make_float2(vv.x + cv.x, vv.y + cv.y);
        }
        float s[4];
#pragma unroll
        for (int u = 0; u < 4; u++) s[u] = q2.x * kc[u].x + q2.y * kc[u].y;
#pragma unroll
        for (int off = 16; off; off >>= 1) {
#pragma unroll
            for (int u = 0; u < 4; u++) s[u] += __shfl_xor_sync(~0u, s[u], off);
        }
#pragma unroll
        for (int u = 0; u < 4; u++) s[u] = s[u] * 0.125f + mb[j0 + u];

        float mc = fmaxf(fmaxf(s[0], s[1]), fmaxf(s[2], s[3]));
        float mn = fmaxf(m, mc);
        float corr = __expf(m - mn);
        float ps = 0.f, ax = 0.f, ay = 0.f;
#pragma unroll
        for (int u = 0; u < 4; u++) {
            float p = __expf(s[u] - mn);
            ps += p;
            ax += p * vc[u].x;
            ay += p * vc[u].y;
        }
        l = l * corr + ps;
        acc.x = acc.x * corr + ax;
        acc.y = acc.y * corr + ay;
        m = mn;
    }
    float invl = 1.0f / l;
    float ox = acc.x * invl, oy = acc.y * invl;
    float bx = tf32r(ox), by = tf32r(oy);
    size_t oidx = ((size_t)bi << 9) + d0;
    *(float2*)(g_ccB + oidx) = make_float2(bx, by);
    *(float2*)(g_ccS + oidx) = make_float2(ox - bx, oy - by);
}

// ---------------- launch ----------------------------------------------------
extern "C" void kernel_launch(void* const* d_in, const int* in_sizes, int n_in,
                              void* d_out, int out_size) {
    const float* x    = (const float*)d_in[0];
    const float* cbk  = (const float*)d_in[1];
    const float* cbv  = (const float*)d_in[2];
    const int*   mask = (const int*)d_in[3];
    const float* Wq = (const float*)d_in[4];
    const float* bq = (const float*)d_in[5];
    const float* Wk = (const float*)d_in[6];
    const float* bk = (const float*)d_in[7];
    const float* Wv = (const float*)d_in[8];
    const float* bv = (const float*)d_in[9];
    const float* Wo = (const float*)d_in[10];
    const float* bo = (const float*)d_in[11];
    const float* alpha1 = (const float*)d_in[12];
    const float* beta1  = (const float*)d_in[13];
    const float* alpha2 = (const float*)d_in[14];
    const float* beta2  = (const float*)d_in[15];
    const float* W1 = (const float*)d_in[16];
    const float* b1 = (const float*)d_in[17];
    const float* W2 = (const float*)d_in[18];
    const float* b2 = (const float*)d_in[19];
    float* out = (float*)d_out;

    float *px2B, *px2S, *pyB, *pyS, *py;
    cudaGetSymbolAddress((void**)&px2B, g_x2B);
    cudaGetSymbolAddress((void**)&px2S, g_x2S);
    cudaGetSymbolAddress((void**)&pyB,  g_y2B);
    cudaGetSymbolAddress((void**)&pyS,  g_y2S);
    cudaGetSymbolAddress((void**)&py,   g_y);

    // 0) split all weights into tf32 big/small planes (3.1M float4s)
    split_weights_kernel<<<3072, 256>>>(Wq, Wk, Wv, Wo, W1, W2);
    // 1) LN1 -> split x2
    ln_split_kernel<<<512, 256>>>(x, alpha1, beta1, px2B, px2S);
    // 2) fused Q,K,V projections (grid 8x16x3 = 384 CTAs)
    gemm_qkv_kernel<<<dim3(8, 16, 3), 128>>>(bq, bk, bv);
    // 3) fused attention (streams both 256MB bias tensors once) -> split concat
    attn_kernel<<<512, 256>>>(cbk, cbv, mask);
    // 4) output projection + residual(x) -> y
    gemm_wo_kernel<<<dim3(8, 16), 128>>>(bo, x);
    // 5) LN2 -> split y2
    ln_split_kernel<<<512, 256>>>(py, alpha2, beta2, pyB, pyS);
    // 6) FFN up + ReLU -> split h (grid 32x16 = 512 CTAs)
    gemm_ffn1_kernel<<<dim3(32, 16), 128>>>(b1);
    // 7) FFN down + residual(y) -> final output
    gemm_ffn2_kernel<<<dim3(8, 16), 128>>>(b2, out);
}

// round 9
// speedup vs baseline: 1.7340x; 1.1640x over previous
#include <cuda_runtime.h>
#include <math.h>

#define SEQ 512   // b*s rows
#define DM  512
#define DF  2048
#define NCH 4     // attention j-chunks
#define JPC 64    // j per chunk

// ---------------- scratch (device globals; no allocation allowed) -----------
__device__ float g_x2B[SEQ*DM], g_x2S[SEQ*DM];
__device__ float g_q[SEQ*DM], g_k[SEQ*DM], g_v[SEQ*DM];
__device__ float g_ccB[SEQ*DM], g_ccS[SEQ*DM];
__device__ float g_y[SEQ*DM];
__device__ float g_y2B[SEQ*DM], g_y2S[SEQ*DM];
__device__ float g_hB[SEQ*DF], g_hS[SEQ*DF];
__device__ float g_scr4[NCH*SEQ*DM];       // attn partial acc / ffn2 split-K partials
__device__ float g_pml[NCH*SEQ*8*2];       // attn partial (m,l) per chunk/row/head
__device__ float g_WqB[DM*DM], g_WqS[DM*DM];
__device__ float g_WkB[DM*DM], g_WkS[DM*DM];
__device__ float g_WvB[DM*DM], g_WvS[DM*DM];
__device__ float g_WoB[DM*DM], g_WoS[DM*DM];
__device__ float g_W1B[DF*DM], g_W1S[DF*DM];
__device__ float g_W2B[DM*DF], g_W2S[DM*DF];

// ---------------- helpers ----------------------------------------------------
__device__ __forceinline__ float tf32r(float x) {
    unsigned r;
    asm("cvt.rna.tf32.f32 %0, %1;" : "=r"(r) : "f"(x));
    return __uint_as_float(r);
}

__device__ __forceinline__ void mma_tf32(float c[4],
                                         unsigned a0, unsigned a1, unsigned a2, unsigned a3,
                                         unsigned b0, unsigned b1) {
    asm volatile(
        "mma.sync.aligned.m16n8k8.row.col.f32.tf32.tf32.f32 "
        "{%0,%1,%2,%3}, {%4,%5,%6,%7}, {%8,%9}, {%0,%1,%2,%3};"
        : "+f"(c[0]), "+f"(c[1]), "+f"(c[2]), "+f"(c[3])
        : "r"(a0), "r"(a1), "r"(a2), "r"(a3), "r"(b0), "r"(b1));
}

// ---------------- weight splitting (big/small tf32 planes) -------------------
__global__ __launch_bounds__(256) void split_weights_kernel(
    const float* __restrict__ Wq, const float* __restrict__ Wk,
    const float* __restrict__ Wv, const float* __restrict__ Wo,
    const float* __restrict__ W1, const float* __restrict__ W2) {
    int i = blockIdx.x * 256 + threadIdx.x;
    const int S = 65536, L = 262144;
    const float* src; float* dB; float* dS; int o;
    if (i < 4 * S) {
        int w = i / S; o = i - w * S;
        src = (w == 0) ? Wq : (w == 1) ? Wk : (w == 2) ? Wv : Wo;
        dB  = (w == 0) ? g_WqB : (w == 1) ? g_WkB : (w == 2) ? g_WvB : g_WoB;
        dS  = (w == 0) ? g_WqS : (w == 1) ? g_WkS : (w == 2) ? g_WvS : g_WoS;
    } else if (i < 4 * S + L) {
        o = i - 4 * S; src = W1; dB = g_W1B; dS = g_W1S;
    } else {
        o = i - 4 * S - L; src = W2; dB = g_W2B; dS = g_W2S;
    }
    float4 v = ((const float4*)src)[o];
    float4 b, s;
    b.x = tf32r(v.x); s.x = tf32r(v.x - b.x);
    b.y = tf32r(v.y); s.y = tf32r(v.y - b.y);
    b.z = tf32r(v.z); s.z = tf32r(v.z - b.z);
    b.w = tf32r(v.w); s.w = tf32r(v.w - b.w);
    ((float4*)dB)[o] = b;
    ((float4*)dS)[o] = s;
}

// ---------------- LayerNorm (ddof=1) with split output -----------------------
__global__ __launch_bounds__(256) void ln_split_kernel(
    const float* __restrict__ x, const float* __restrict__ alpha,
    const float* __restrict__ beta, float* __restrict__ outB,
    float* __restrict__ outS) {
    int row = blockIdx.x;
    int t = threadIdx.x;
    float2 v = ((const float2*)(x + (size_t)row * 512))[t];
    float s = v.x + v.y;
    float q = v.x * v.x + v.y * v.y;
    __shared__ float ssum[8], ssq[8];
#pragma unroll
    for (int off = 16; off; off >>= 1) {
        s += __shfl_xor_sync(~0u, s, off);
        q += __shfl_xor_sync(~0u, q, off);
    }
    int w = t >> 5, l = t & 31;
    if (l == 0) { ssum[w] = s; ssq[w] = q; }
    __syncthreads();
    float tot = 0.f, totq = 0.f;
#pragma unroll
    for (int i = 0; i < 8; i++) { tot += ssum[i]; totq += ssq[i]; }
    float mu  = tot * (1.0f / 512.0f);
    float var = (totq - 512.0f * mu * mu) * (1.0f / 511.0f);
    float inv = 1.0f / (sqrtf(var) + 1e-6f);
    float2 a  = ((const float2*)alpha)[t];
    float2 bb = ((const float2*)beta)[t];
    float ox = a.x * (v.x - mu) * inv + bb.x;
    float oy = a.y * (v.y - mu) * inv + bb.y;
    float bx = tf32r(ox), by = tf32r(oy);
    ((float2*)(outB + (size_t)row * 512))[t] = make_float2(bx, by);
    ((float2*)(outS + (size_t)row * 512))[t] = make_float2(ox - bx, oy - by);
}

// ---------------- 3xTF32 GEMM on pre-split planes ---------------------------
// C[*,N] tile = A[32 rows, kLen] @ B[64 rows, kLen]^T with row strides lda/ldb.
__device__ __forceinline__ void gemm_body(
    const float* __restrict__ AB, const float* __restrict__ AS,
    const float* __restrict__ BB, const float* __restrict__ BS,
    const float* __restrict__ bias, const float* __restrict__ Res,
    float* __restrict__ C, float* __restrict__ CB, float* __restrict__ CS,
    int N, int lda, int ldb, int kLen, int relu) {
    __shared__ float sAB[32][36], sAS[32][36];
    __shared__ float sBB[64][36], sBS[64][36];
    int tid = threadIdx.x;
    int m0 = blockIdx.y * 32, n0 = blockIdx.x * 64;
    int ra = tid >> 2, ka = (tid & 3) * 8;
    int rb = tid >> 1, kb = (tid & 1) * 16;
    const float* pAB = AB + (size_t)(m0 + ra) * lda + ka;
    const float* pAS = AS + (size_t)(m0 + ra) * lda + ka;
    const float* pBB = BB + (size_t)(n0 + rb) * ldb + kb;
    const float* pBS = BS + (size_t)(n0 + rb) * ldb + kb;

    int w = tid >> 5, lane = tid & 31;
    int g = lane >> 2, tg = lane & 3;

    float acc[2][2][4] = {};

    float4 rAB[2], rAS[2], rBB[4], rBS[4];
    rAB[0] = *(const float4*)(pAB); rAB[1] = *(const float4*)(pAB + 4);
    rAS[0] = *(const float4*)(pAS); rAS[1] = *(const float4*)(pAS + 4);
#pragma unroll
    for (int i = 0; i < 4; i++) {
        rBB[i] = *(const float4*)(pBB + i * 4);
        rBS[i] = *(const float4*)(pBS + i * 4);
    }

    for (int k0 = 0; k0 < kLen; k0 += 32) {
        __syncthreads();
#pragma unroll
        for (int i = 0; i < 8; i++) {
            sAB[ra][ka + i] = ((const float*)rAB)[i];
            sAS[ra][ka + i] = ((const float*)rAS)[i];
        }
#pragma unroll
        for (int i = 0; i < 16; i++) {
            sBB[rb][kb + i] = ((const float*)rBB)[i];
            sBS[rb][kb + i] = ((const float*)rBS)[i];
        }
        __syncthreads();
        if (k0 + 32 < kLen) {
            pAB += 32; pAS += 32; pBB += 32; pBS += 32;
            rAB[0] = *(const float4*)(pAB); rAB[1] = *(const float4*)(pAB + 4);
            rAS[0] = *(const float4*)(pAS); rAS[1] = *(const float4*)(pAS + 4);
#pragma unroll
            for (int i = 0; i < 4; i++) {
                rBB[i] = *(const float4*)(pBB + i * 4);
                rBS[i] = *(const float4*)(pBS + i * 4);
            }
        }
#pragma unroll
        for (int kk = 0; kk < 32; kk += 8) {
            unsigned aB[2][4], aS[2][4], bB[2][2], bS[2][2];
#pragma unroll
            for (int mt = 0; mt < 2; mt++) {
                int r0 = mt * 16 + g;
                aB[mt][0] = __float_as_uint(sAB[r0][kk + tg]);
                aB[mt][1] = __float_as_uint(sAB[r0 + 8][kk + tg]);
                aB[mt][2] = __float_as_uint(sAB[r0][kk + tg + 4]);
                aB[mt][3] = __float_as_uint(sAB[r0 + 8][kk + tg + 4]);
                aS[mt][0] = __float_as_uint(sAS[r0][kk + tg]);
                aS[mt][1] = __float_as_uint(sAS[r0 + 8][kk + tg]);
                aS[mt][2] = __float_as_uint(sAS[r0][kk + tg + 4]);
                aS[mt][3] = __float_as_uint(sAS[r0 + 8][kk + tg + 4]);
            }
#pragma unroll
            for (int nt = 0; nt < 2; nt++) {
                int c0 = w * 16 + nt * 8 + g;
                bB[nt][0] = __float_as_uint(sBB[c0][kk + tg]);
                bB[nt][1] = __float_as_uint(sBB[c0][kk + tg + 4]);
                bS[nt][0] = __float_as_uint(sBS[c0][kk + tg]);
                bS[nt][1] = __float_as_uint(sBS[c0][kk + tg + 4]);
            }
#pragma unroll
            for (int mt = 0; mt < 2; mt++)
#pragma unroll
                for (int nt = 0; nt < 2; nt++) {
                    mma_tf32(acc[mt][nt], aB[mt][0], aB[mt][1], aB[mt][2], aB[mt][3],
                             bB[nt][0], bB[nt][1]);
                    mma_tf32(acc[mt][nt], aB[mt][0], aB[mt][1], aB[mt][2], aB[mt][3],
                             bS[nt][0], bS[nt][1]);
                    mma_tf32(acc[mt][nt], aS[mt][0], aS[mt][1], aS[mt][2], aS[mt][3],
                             bB[nt][0], bB[nt][1]);
                }
        }
    }
#pragma unroll
    for (int mt = 0; mt < 2; mt++)
#pragma unroll
        for (int nt = 0; nt < 2; nt++) {
            int row = m0 + mt * 16 + g;
            int col = n0 + w * 16 + nt * 8 + tg * 2;
            float2 bz = bias ? *(const float2*)(bias + col) : make_float2(0.f, 0.f);
#pragma unroll
            for (int h = 0; h < 2; h++) {
                int rr = row + h * 8;
                float cx = acc[mt][nt][h * 2 + 0] + bz.x;
                float cy = acc[mt][nt][h * 2 + 1] + bz.y;
                if (relu) { cx = fmaxf(cx, 0.f); cy = fmaxf(cy, 0.f); }
                if (Res) {
                    float2 rv = *(const float2*)(Res + (size_t)rr * N + col);
                    cx += rv.x; cy += rv.y;
                }
                if (C)
                    *(float2*)(C + (size_t)rr * N + col) = make_float2(cx, cy);
                if (CB) {
                    float bx = tf32r(cx), by = tf32r(cy);
                    *(float2*)(CB + (size_t)rr * N + col) = make_float2(bx, by);
                    *(float2*)(CS + (size_t)rr * N + col) =
                        make_float2(cx - bx, cy - by);
                }
            }
        }
}

__global__ __launch_bounds__(128) void gemm_qkv_kernel(
    const float* __restrict__ bq, const float* __restrict__ bk,
    const float* __restrict__ bv) {
    const float *BB, *BS, *bias; float* C;
    if (blockIdx.z == 0)      { BB = g_WqB; BS = g_WqS; bias = bq; C = g_q; }
    else if (blockIdx.z == 1) { BB = g_WkB; BS = g_WkS; bias = bk; C = g_k; }
    else                      { BB = g_WvB; BS = g_WvS; bias = bv; C = g_v; }
    gemm_body(g_x2B, g_x2S, BB, BS, bias, nullptr, C, nullptr, nullptr,
              512, 512, 512, 512, 0);
}

__global__ __launch_bounds__(128) void gemm_wo_kernel(
    const float* __restrict__ bo, const float* __restrict__ x) {
    gemm_body(g_ccB, g_ccS, g_WoB, g_WoS, bo, x, g_y, nullptr, nullptr,
              512, 512, 512, 512, 0);
}

__global__ __launch_bounds__(128) void gemm_ffn1_kernel(
    const float* __restrict__ b1) {
    gemm_body(g_y2B, g_y2S, g_W1B, g_W1S, b1, nullptr, nullptr, g_hB, g_hS,
              2048, 512, 512, 512, 1);
}

// FFN2 split-K: slice s handles k in [s*512, s*512+512); partial to g_scr4
__global__ __launch_bounds__(128) void gemm_ffn2_part_kernel() {
    int s = blockIdx.z;
    gemm_body(g_hB + s * 512, g_hS + s * 512,
              g_W2B + s * 512, g_W2S + s * 512,
              nullptr, nullptr, g_scr4 + (size_t)s * SEQ * DM, nullptr, nullptr,
              512, 2048, 2048, 512, 0);
}

__global__ __launch_bounds__(128) void ffn2_reduce_kernel(
    const float* __restrict__ b2, float* __restrict__ out) {
    int idx = blockIdx.x * 128 + threadIdx.x;       // float4 index, 65536 total
    int row = idx >> 7, c4 = (idx & 127) * 4;
    size_t o = (size_t)row * 512 + c4;
    float4 a0 = *(const float4*)(g_scr4 + o);
    float4 a1 = *(const float4*)(g_scr4 + SEQ * DM + o);
    float4 a2 = *(const float4*)(g_scr4 + 2 * SEQ * DM + o);
    float4 a3 = *(const float4*)(g_scr4 + (size_t)3 * SEQ * DM + o);
    float4 bz = *(const float4*)(b2 + c4);
    float4 rv = *(const float4*)(g_y + o);
    float4 r;
    r.x = a0.x + a1.x + a2.x + a3.x + bz.x + rv.x;
    r.y = a0.y + a1.y + a2.y + a3.y + bz.y + rv.y;
    r.z = a0.z + a1.z + a2.z + a3.z + bz.z + rv.z;
    r.w = a0.w + a1.w + a2.w + a3.w + bz.w + rv.w;
    *(float4*)(out + o) = r;
}

// ---------------- attention: split-j partial pass ---------------------------
// grid (bi=512, chunk=4), block 128. Warp covers 2 heads; lane: 4 dims (float4).
__global__ __launch_bounds__(128) void attn_part_kernel(
    const float* __restrict__ cbk, const float* __restrict__ cbv,
    const int* __restrict__ mask) {
    int bi = blockIdx.x;
    int ch = blockIdx.y;
    int b = bi >> 8, i = bi & 255;
    int tid = threadIdx.x;
    int w = tid >> 5, lane = tid & 31;
    int h = (w << 1) + (lane >> 4);          // head 0..7
    int d0 = (h << 6) + ((lane & 15) << 2);  // dim offset, float4 aligned

    __shared__ float mb[JPC];
    if (tid < JPC)
        mb[tid] = (mask[(b << 8) + ch * JPC + tid] == 1) ? -1e9f : 0.0f;
    __syncthreads();

    const float4 q4 = *(const float4*)(g_q + ((size_t)bi << 9) + d0);
    const float* kp = g_k + (((size_t)b << 8) << 9) + d0;   // + j*512
    const float* vp = g_v + (((size_t)b << 8) << 9) + d0;
    const size_t cb_base = (size_t)b * 33554432 + (size_t)i * 512 + d0;
    const float* ckp = cbk + cb_base;                        // + j*131072
    const float* cvp = cbv + cb_base;

    float m = -INFINITY, l = 0.0f;
    float4 acc = make_float4(0.f, 0.f, 0.f, 0.f);

    int jbase = ch * JPC;
    for (int j0 = 0; j0 < JPC; j0 += 4) {
        float4 kc[4], vc[4];
#pragma unroll
        for (int u = 0; u < 4; u++) {
            size_t j = (size_t)(jbase + j0 + u);
            float4 kk = *(const float4*)(kp + j * 512);
            float4 ck = *(const float4*)(ckp + j * 131072);
            float4 vv = *(const float4*)(vp + j * 512);
            float4 cv = *(const float4*)(cvp + j * 131072);
            kc[u] = make_float4(kk.x + ck.x, kk.y + ck.y, kk.z + ck.z, kk.w + ck.w);
            vc[u] = make_float4(vv.x + cv.x, vv.y + cv.y, vv.z + cv.z, vv.w + cv.w);
        }
        float s[4];
#pragma unroll
        for (int u = 0; u < 4; u++)
            s[u] = q4.x * kc[u].x + q4.y * kc[u].y + q4.z * kc[u].z + q4.w * kc[u].w;
#pragma unroll
        for (int off = 8; off; off >>= 1) {
#pragma unroll
            for (int u = 0; u < 4; u++) s[u] += __shfl_xor_sync(~0u, s[u], off);
        }
#pragma unroll
        for (int u = 0; u < 4; u++) s[u] = s[u] * 0.125f + mb[j0 + u];

        float mc = fmaxf(fmaxf(s[0], s[1]), fmaxf(s[2], s[3]));
        float mn = fmaxf(m, mc);
        float corr = __expf(m - mn);
        float ps = 0.f;
        float4 av = make_float4(0.f, 0.f, 0.f, 0.f);
#pragma unroll
        for (int u = 0; u < 4; u++) {
            float p = __expf(s[u] - mn);
            ps += p;
            av.x += p * vc[u].x; av.y += p * vc[u].y;
            av.z += p * vc[u].z; av.w += p * vc[u].w;
        }
        l = l * corr + ps;
        acc.x = acc.x * corr + av.x; acc.y = acc.y * corr + av.y;
        acc.z = acc.z * corr + av.z; acc.w = acc.w * corr + av.w;
        m = mn;
    }
    *(float4*)(g_scr4 + ((size_t)(ch * SEQ + bi) << 9) + d0) = acc;
    if ((lane & 15) == 0)
        *(float2*)(g_pml + ((size_t)(ch * SEQ + bi) * 8 + h) * 2) = make_float2(m, l);
}

// combine 4 chunk partials -> split concat planes
__global__ __launch_bounds__(128) void attn_combine_kernel() {
    int bi = blockIdx.x;
    int t = threadIdx.x;
    int d0 = t << 2;
    int h = d0 >> 6;
    float mm[NCH], ll[NCH];
    float M = -INFINITY;
#pragma unroll
    for (int c = 0; c < NCH; c++) {
        float2 ml = *(const float2*)(g_pml + ((size_t)(c * SEQ + bi) * 8 + h) * 2);
        mm[c] = ml.x; ll[c] = ml.y;
        M = fmaxf(M, ml.x);
    }
    float L = 0.f;
    float4 a = make_float4(0.f, 0.f, 0.f, 0.f);
#pragma unroll
    for (int c = 0; c < NCH; c++) {
        float wgt = __expf(mm[c] - M);
        L += ll[c] * wgt;
        float4 p = *(const float4*)(g_scr4 + ((size_t)(c * SEQ + bi) << 9) + d0);
        a.x += p.x * wgt; a.y += p.y * wgt; a.z += p.z * wgt; a.w += p.w * wgt;
    }
    float inv = 1.0f / L;
    float ox = a.x * inv, oy = a.y * inv, oz = a.z * inv, ow = a.w * inv;
    float bx = tf32r(ox), by = tf32r(oy), bz = tf32r(oz), bw = tf32r(ow);
    size_t o = ((size_t)bi << 9) + d0;
    *(float4*)(g_ccB + o) = make_float4(bx, by, bz, bw);
    *(float4*)(g_ccS + o) = make_float4(ox - bx, oy - by, oz - bz, ow - bw);
}

// ---------------- launch ----------------------------------------------------
extern "C" void kernel_launch(void* const* d_in, const int* in_sizes, int n_in,
                              void* d_out, int out_size) {
    const float* x    = (const float*)d_in[0];
    const float* cbk  = (const float*)d_in[1];
    const float* cbv  = (const float*)d_in[2];
    const int*   mask = (const int*)d_in[3];
    const float* Wq = (const float*)d_in[4];
    const float* bq = (const float*)d_in[5];
    const float* Wk = (const float*)d_in[6];
    const float* bk = (const float*)d_in[7];
    const float* Wv = (const float*)d_in[8];
    const float* bv = (const float*)d_in[9];
    const float* Wo = (const float*)d_in[10];
    const float* bo = (const float*)d_in[11];
    const float* alpha1 = (const float*)d_in[12];
    const float* beta1  = (const float*)d_in[13];
    const float* alpha2 = (const float*)d_in[14];
    const float* beta2  = (const float*)d_in[15];
    const float* W1 = (const float*)d_in[16];
    const float* b1 = (const float*)d_in[17];
    const float* W2 = (const float*)d_in[18];
    const float* b2 = (const float*)d_in[19];
    float* out = (float*)d_out;

    float *px2B, *px2S, *pyB, *pyS, *py;
    cudaGetSymbolAddress((void**)&px2B, g_x2B);
    cudaGetSymbolAddress((void**)&px2S, g_x2S);
    cudaGetSymbolAddress((void**)&pyB,  g_y2B);
    cudaGetSymbolAddress((void**)&pyS,  g_y2S);
    cudaGetSymbolAddress((void**)&py,   g_y);

    // 0) split all weights into tf32 big/small planes
    split_weights_kernel<<<3072, 256>>>(Wq, Wk, Wv, Wo, W1, W2);
    // 1) LN1 -> split x2
    ln_split_kernel<<<512, 256>>>(x, alpha1, beta1, px2B, px2S);
    // 2) fused Q,K,V projections
    gemm_qkv_kernel<<<dim3(8, 16, 3), 128>>>(bq, bk, bv);
    // 3) attention: 4-way split-j partials (2048 CTAs) + combine
    attn_part_kernel<<<dim3(512, NCH), 128>>>(cbk, cbv, mask);
    attn_combine_kernel<<<512, 128>>>();
    // 4) output projection + residual(x) -> y
    gemm_wo_kernel<<<dim3(8, 16), 128>>>(bo, x);
    // 5) LN2 -> split y2
    ln_split_kernel<<<512, 256>>>(py, alpha2, beta2, pyB, pyS);
    // 6) FFN up + ReLU -> split h
    gemm_ffn1_kernel<<<dim3(32, 16), 128>>>(b1);
    // 7) FFN down split-K=4 partials + reduce(+bias+residual) -> out
    gemm_ffn2_part_kernel<<<dim3(8, 16, 4), 128>>>();
    ffn2_reduce_kernel<<<512, 128>>>(b2, out);
}

// round 11
// speedup vs baseline: 2.8719x; 1.6563x over previous
#include <cuda_runtime.h>
#include <cuda_bf16.h>
#include <math.h>

#define SEQ 512   // b*s rows
#define DM  512
#define DF  2048
#define NCH 4     // attention j-chunks
#define JPC 64    // j per chunk

// ---------------- scratch (device globals; no allocation allowed) -----------
// packed bf16x2 planes (big/small) for GEMM A/B operands
__device__ unsigned g_x2B[SEQ*DM/2], g_x2S[SEQ*DM/2];
__device__ float    g_q[SEQ*DM], g_k[SEQ*DM], g_v[SEQ*DM];
__device__ unsigned g_ccB[SEQ*DM/2], g_ccS[SEQ*DM/2];
__device__ float    g_y[SEQ*DM];
__device__ unsigned g_y2B[SEQ*DM/2], g_y2S[SEQ*DM/2];
__device__ unsigned g_hB[SEQ*DF/2], g_hS[SEQ*DF/2];
__device__ float    g_scr4[NCH*SEQ*DM];   // attn partials / ffn2 split-K partials
__device__ float    g_pml[NCH*SEQ*8*2];   // attn partial (m,l)
__device__ unsigned g_WqB[DM*DM/2], g_WqS[DM*DM/2];
__device__ unsigned g_WkB[DM*DM/2], g_WkS[DM*DM/2];
__device__ unsigned g_WvB[DM*DM/2], g_WvS[DM*DM/2];
__device__ unsigned g_WoB[DM*DM/2], g_WoS[DM*DM/2];
__device__ unsigned g_W1B[DF*DM/2], g_W1S[DF*DM/2];
__device__ unsigned g_W2B[DM*DF/2], g_W2S[DM*DF/2];

// ---------------- helpers ----------------------------------------------------
// split (x0,x1) into packed bf16x2 big word (returned) + small word (out-param)
__device__ __forceinline__ unsigned packsplit(float x0, float x1, unsigned& small) {
    __nv_bfloat16 b0 = __float2bfloat16_rn(x0);
    __nv_bfloat16 b1 = __float2bfloat16_rn(x1);
    float r0 = x0 - __bfloat162float(b0);
    float r1 = x1 - __bfloat162float(b1);
    __nv_bfloat16 s0 = __float2bfloat16_rn(r0);
    __nv_bfloat16 s1 = __float2bfloat16_rn(r1);
    small = (unsigned)__bfloat16_as_ushort(s0) |
            ((unsigned)__bfloat16_as_ushort(s1) << 16);
    return (unsigned)__bfloat16_as_ushort(b0) |
           ((unsigned)__bfloat16_as_ushort(b1) << 16);
}

__device__ __forceinline__ void mma_bf16(float c[4],
                                         unsigned a0, unsigned a1, unsigned a2, unsigned a3,
                                         unsigned b0, unsigned b1) {
    asm volatile(
        "mma.sync.aligned.m16n8k16.row.col.f32.bf16.bf16.f32 "
        "{%0,%1,%2,%3}, {%4,%5,%6,%7}, {%8,%9}, {%0,%1,%2,%3};"
        : "+f"(c[0]), "+f"(c[1]), "+f"(c[2]), "+f"(c[3])
        : "r"(a0), "r"(a1), "r"(a2), "r"(a3), "r"(b0), "r"(b1));
}

// ---------------- weight splitting (big/small bf16 packed planes) -----------
__global__ __launch_bounds__(256) void split_weights_kernel(
    const float* __restrict__ Wq, const float* __restrict__ Wk,
    const float* __restrict__ Wv, const float* __restrict__ Wo,
    const float* __restrict__ W1, const float* __restrict__ W2) {
    int i = blockIdx.x * 256 + threadIdx.x;   // float8 index, total 393216
    const int S8 = 32768, L8 = 131072;
    const float* src; unsigned* dB; unsigned* dS; int o;
    if (i < 4 * S8) {
        int w = i >> 15; o = i & 32767;
        src = (w == 0) ? Wq : (w == 1) ? Wk : (w == 2) ? Wv : Wo;
        dB  = (w == 0) ? g_WqB : (w == 1) ? g_WkB : (w == 2) ? g_WvB : g_WoB;
        dS  = (w == 0) ? g_WqS : (w == 1) ? g_WkS : (w == 2) ? g_WvS : g_WoS;
    } else if (i < 4 * S8 + L8) {
        o = i - 4 * S8; src = W1; dB = g_W1B; dS = g_W1S;
    } else {
        o = i - 4 * S8 - L8; src = W2; dB = g_W2B; dS = g_W2S;
    }
    float4 v0 = ((const float4*)src)[o * 2];
    float4 v1 = ((const float4*)src)[o * 2 + 1];
    uint4 big, sml;
    big.x = packsplit(v0.x, v0.y, sml.x);
    big.y = packsplit(v0.z, v0.w, sml.y);
    big.z = packsplit(v1.x, v1.y, sml.z);
    big.w = packsplit(v1.z, v1.w, sml.w);
    ((uint4*)dB)[o] = big;
    ((uint4*)dS)[o] = sml;
}

// ---------------- LayerNorm (ddof=1) with packed split output ----------------
__global__ __launch_bounds__(256) void ln_split_kernel(
    const float* __restrict__ x, const float* __restrict__ alpha,
    const float* __restrict__ beta, unsigned* __restrict__ outB,
    unsigned* __restrict__ outS) {
    int row = blockIdx.x;
    int t = threadIdx.x;
    float2 v = ((const float2*)(x + (size_t)row * 512))[t];
    float s = v.x + v.y;
    float q = v.x * v.x + v.y * v.y;
    __shared__ float ssum[8], ssq[8];
#pragma unroll
    for (int off = 16; off; off >>= 1) {
        s += __shfl_xor_sync(~0u, s, off);
        q += __shfl_xor_sync(~0u, q, off);
    }
    int w = t >> 5, l = t & 31;
    if (l == 0) { ssum[w] = s; ssq[w] = q; }
    __syncthreads();
    float tot = 0.f, totq = 0.f;
#pragma unroll
    for (int i = 0; i < 8; i++) { tot += ssum[i]; totq += ssq[i]; }
    float mu  = tot * (1.0f / 512.0f);
    float var = (totq - 512.0f * mu * mu) * (1.0f / 511.0f);
    float inv = 1.0f / (sqrtf(var) + 1e-6f);
    float2 a  = ((const float2*)alpha)[t];
    float2 bb = ((const float2*)beta)[t];
    float ox = a.x * (v.x - mu) * inv + bb.x;
    float oy = a.y * (v.y - mu) * inv + bb.y;
    unsigned sm;
    unsigned bg = packsplit(ox, oy, sm);
    outB[row * 256 + t] = bg;
    outS[row * 256 + t] = sm;
}

// ---------------- 3x-split-BF16 GEMM on packed planes ------------------------
// C tile = A[32 rows] @ B[64 rows]^T, strides in words (bf16 pairs).
// CTA 32x64, BK = 32 elems = 16 words, 128 threads, 4 warps (warp tile 32x16).
__device__ __forceinline__ void gemm_body(
    const unsigned* __restrict__ AB, const unsigned* __restrict__ AS,
    const unsigned* __restrict__ BB, const unsigned* __restrict__ BS,
    const float* __restrict__ bias, const float* __restrict__ Res,
    float* __restrict__ C, unsigned* __restrict__ CB, unsigned* __restrict__ CS,
    int N, int ldaW, int ldbW, int kWords, int relu) {
    __shared__ unsigned sAB[32][20], sAS[32][20];
    __shared__ unsigned sBB[64][20], sBS[64][20];
    int tid = threadIdx.x;
    int m0 = blockIdx.y * 32, n0 = blockIdx.x * 64;
    int ra = tid >> 2, ca = (tid & 3) * 4;   // A: 1 uint4 (4 words) per plane
    int rb = tid >> 1, cb = (tid & 1) * 8;   // B: 2 uint4 per plane
    const unsigned* pAB = AB + (size_t)(m0 + ra) * ldaW + ca;
    const unsigned* pAS = AS + (size_t)(m0 + ra) * ldaW + ca;
    const unsigned* pBB = BB + (size_t)(n0 + rb) * ldbW + cb;
    const unsigned* pBS = BS + (size_t)(n0 + rb) * ldbW + cb;

    int w = tid >> 5, lane = tid & 31;
    int g = lane >> 2, tg = lane & 3;

    float acc[2][2][4] = {};

    uint4 rA_B, rA_S, rB_B[2], rB_S[2];
    rA_B = *(const uint4*)pAB;
    rA_S = *(const uint4*)pAS;
    rB_B[0] = *(const uint4*)pBB; rB_B[1] = *(const uint4*)(pBB + 4);
    rB_S[0] = *(const uint4*)pBS; rB_S[1] = *(const uint4*)(pBS + 4);

    for (int kw = 0; kw < kWords; kw += 16) {
        __syncthreads();
        *(uint4*)&sAB[ra][ca] = rA_B;
        *(uint4*)&sAS[ra][ca] = rA_S;
        *(uint4*)&sBB[rb][cb] = rB_B[0]; *(uint4*)&sBB[rb][cb + 4] = rB_B[1];
        *(uint4*)&sBS[rb][cb] = rB_S[0]; *(uint4*)&sBS[rb][cb + 4] = rB_S[1];
        __syncthreads();
        if (kw + 16 < kWords) {
            pAB += 16; pAS += 16; pBB += 16; pBS += 16;
            rA_B = *(const uint4*)pAB;
            rA_S = *(const uint4*)pAS;
            rB_B[0] = *(const uint4*)pBB; rB_B[1] = *(const uint4*)(pBB + 4);
            rB_S[0] = *(const uint4*)pBS; rB_S[1] = *(const uint4*)(pBS + 4);
        }
#pragma unroll
        for (int s = 0; s < 16; s += 8) {
            unsigned aB[2][4], aS[2][4], bB[2][2], bS[2][2];
#pragma unroll
            for (int mt = 0; mt < 2; mt++) {
                int r0 = mt * 16 + g;
                aB[mt][0] = sAB[r0][s + tg];
                aB[mt][1] = sAB[r0 + 8][s + tg];
                aB[mt][2] = sAB[r0][s + tg + 4];
                aB[mt][3] = sAB[r0 + 8][s + tg + 4];
                aS[mt][0] = sAS[r0][s + tg];
                aS[mt][1] = sAS[r0 + 8][s + tg];
                aS[mt][2] = sAS[r0][s + tg + 4];
                aS[mt][3] = sAS[r0 + 8][s + tg + 4];
            }
#pragma unroll
            for (int nt = 0; nt < 2; nt++) {
                int c0 = w * 16 + nt * 8 + g;
                bB[nt][0] = sBB[c0][s + tg];
                bB[nt][1] = sBB[c0][s + tg + 4];
                bS[nt][0] = sBS[c0][s + tg];
                bS[nt][1] = sBS[c0][s + tg + 4];
            }
#pragma unroll
            for (int mt = 0; mt < 2; mt++)
#pragma unroll
                for (int nt = 0; nt < 2; nt++) {
                    mma_bf16(acc[mt][nt], aB[mt][0], aB[mt][1], aB[mt][2], aB[mt][3],
                             bB[nt][0], bB[nt][1]);
                    mma_bf16(acc[mt][nt], aB[mt][0], aB[mt][1], aB[mt][2], aB[mt][3],
                             bS[nt][0], bS[nt][1]);
                    mma_bf16(acc[mt][nt], aS[mt][0], aS[mt][1], aS[mt][2], aS[mt][3],
                             bB[nt][0], bB[nt][1]);
                }
        }
    }
    int NW = N >> 1;
#pragma unroll
    for (int mt = 0; mt < 2; mt++)
#pragma unroll
        for (int nt = 0; nt < 2; nt++) {
            int row = m0 + mt * 16 + g;
            int col = n0 + w * 16 + nt * 8 + tg * 2;
            float2 bz = bias ? *(const float2*)(bias + col) : make_float2(0.f, 0.f);
#pragma unroll
            for (int h = 0; h < 2; h++) {
                int rr = row + h * 8;
                float cx = acc[mt][nt][h * 2 + 0] + bz.x;
                float cy = acc[mt][nt][h * 2 + 1] + bz.y;
                if (relu) { cx = fmaxf(cx, 0.f); cy = fmaxf(cy, 0.f); }
                if (Res) {
                    float2 rv = *(const float2*)(Res + (size_t)rr * N + col);
                    cx += rv.x; cy += rv.y;
                }
                if (C)
                    *(float2*)(C + (size_t)rr * N + col) = make_float2(cx, cy);
                if (CB) {
                    unsigned sm;
                    unsigned bg = packsplit(cx, cy, sm);
                    CB[(size_t)rr * NW + (col >> 1)] = bg;
                    CS[(size_t)rr * NW + (col >> 1)] = sm;
                }
            }
        }
}

__global__ __launch_bounds__(128) void gemm_qkv_kernel(
    const float* __restrict__ bq, const float* __restrict__ bk,
    const float* __restrict__ bv) {
    const unsigned *BB, *BS; const float* bias; float* C;
    if (blockIdx.z == 0)      { BB = g_WqB; BS = g_WqS; bias = bq; C = g_q; }
    else if (blockIdx.z == 1) { BB = g_WkB; BS = g_WkS; bias = bk; C = g_k; }
    else                      { BB = g_WvB; BS = g_WvS; bias = bv; C = g_v; }
    gemm_body(g_x2B, g_x2S, BB, BS, bias, nullptr, C, nullptr, nullptr,
              512, 256, 256, 256, 0);
}

__global__ __launch_bounds__(128) void gemm_wo_kernel(
    const float* __restrict__ bo, const float* __restrict__ x) {
    gemm_body(g_ccB, g_ccS, g_WoB, g_WoS, bo, x, g_y, nullptr, nullptr,
              512, 256, 256, 256, 0);
}

__global__ __launch_bounds__(128) void gemm_ffn1_kernel(
    const float* __restrict__ b1) {
    gemm_body(g_y2B, g_y2S, g_W1B, g_W1S, b1, nullptr, nullptr, g_hB, g_hS,
              2048, 256, 256, 256, 1);
}

// FFN2 split-K: slice s handles k-words [s*256, s*256+256)
__global__ __launch_bounds__(128) void gemm_ffn2_part_kernel() {
    int s = blockIdx.z;
    gemm_body(g_hB + s * 256, g_hS + s * 256,
              g_W2B + s * 256, g_W2S + s * 256,
              nullptr, nullptr, g_scr4 + (size_t)s * SEQ * DM, nullptr, nullptr,
              512, 1024, 1024, 256, 0);
}

__global__ __launch_bounds__(128) void ffn2_reduce_kernel(
    const float* __restrict__ b2, float* __restrict__ out) {
    int idx = blockIdx.x * 128 + threadIdx.x;
    int row = idx >> 7, c4 = (idx & 127) * 4;
    size_t o = (size_t)row * 512 + c4;
    float4 a0 = *(const float4*)(g_scr4 + o);
    float4 a1 = *(const float4*)(g_scr4 + SEQ * DM + o);
    float4 a2 = *(const float4*)(g_scr4 + 2 * SEQ * DM + o);
    float4 a3 = *(const float4*)(g_scr4 + (size_t)3 * SEQ * DM + o);
    float4 bz = *(const float4*)(b2 + c4);
    float4 rv = *(const float4*)(g_y + o);
    float4 r;
    r.x = a0.x + a1.x + a2.x + a3.x + bz.x + rv.x;
    r.y = a0.y + a1.y + a2.y + a3.y + bz.y + rv.y;
    r.z = a0.z + a1.z + a2.z + a3.z + bz.z + rv.z;
    r.w = a0.w + a1.w + a2.w + a3.w + bz.w + rv.w;
    *(float4*)(out + o) = r;
}

// ---------------- attention: 3-phase split-j partial pass --------------------
// grid (bi=512, chunk=4), block 128. Warp = 2 heads; lane16 covers 4 dims.
// Phase 1: scores (k+cbk stream) -> smem. Phase 2: softmax (once).
// Phase 3: PV accumulation (v+cbv stream) with p from smem.
__global__ __launch_bounds__(128, 8) void attn_part_kernel(
    const float* __restrict__ cbk, const float* __restrict__ cbv,
    const int* __restrict__ mask) {
    int bi = blockIdx.x;
    int ch = blockIdx.y;
    int b = bi >> 8, i = bi & 255;
    int tid = threadIdx.x;
    int w = tid >> 5, lane = tid & 31;
    int h = (w << 1) + (lane >> 4);          // head 0..7
    int l16 = lane & 15;
    int d0 = (h << 6) + (l16 << 2);          // dim offset, float4 aligned

    __shared__ float mb[JPC];
    __shared__ float sp[8][JPC];             // scores then p
    if (tid < JPC)
        mb[tid] = (mask[(b << 8) + ch * JPC + tid] == 1) ? -1e9f : 0.0f;
    __syncthreads();

    const float4 q4 = *(const float4*)(g_q + ((size_t)bi << 9) + d0);
    const float* kp = g_k + (((size_t)b << 8) << 9) + d0;   // + j*512
    const float* vp = g_v + (((size_t)b << 8) << 9) + d0;
    const size_t cb_base = (size_t)b * 33554432 + (size_t)i * 512 + d0;
    const float* ckp = cbk + cb_base;                        // + j*131072
    const float* cvp = cbv + cb_base;
    int jbase = ch * JPC;

    // ---- phase 1: raw scores ----
    for (int j0 = 0; j0 < JPC; j0 += 4) {
        float s[4];
#pragma unroll
        for (int u = 0; u < 4; u++) {
            size_t j = (size_t)(jbase + j0 + u);
            float4 kk = *(const float4*)(kp + j * 512);
            float4 ck = *(const float4*)(ckp + j * 131072);
            s[u] = q4.x * kk.x + q4.y * kk.y + q4.z * kk.z + q4.w * kk.w
                 + q4.x * ck.x + q4.y * ck.y + q4.z * ck.z + q4.w * ck.w;
        }
#pragma unroll
        for (int off = 8; off; off >>= 1) {
#pragma unroll
            for (int u = 0; u < 4; u++) s[u] += __shfl_xor_sync(~0u, s[u], off);
        }
        if (l16 == 0) {
#pragma unroll
            for (int u = 0; u < 4; u++) sp[h][j0 + u] = s[u];
        }
    }
    __syncwarp();

    // ---- phase 2: softmax over this chunk (lane16 handles 4 j's) ----
    int jm = l16 * 4;
    float sc[4];
#pragma unroll
    for (int t = 0; t < 4; t++)
        sc[t] = sp[h][jm + t] * 0.125f + mb[jm + t];
    float m4 = fmaxf(fmaxf(sc[0], sc[1]), fmaxf(sc[2], sc[3]));
#pragma unroll
    for (int off = 8; off; off >>= 1)
        m4 = fmaxf(m4, __shfl_xor_sync(~0u, m4, off));
    float p[4], l4 = 0.f;
#pragma unroll
    for (int t = 0; t < 4; t++) {
        p[t] = __expf(sc[t] - m4);
        l4 += p[t];
    }
#pragma unroll
    for (int off = 8; off; off >>= 1)
        l4 += __shfl_xor_sync(~0u, l4, off);
#pragma unroll
    for (int t = 0; t < 4; t++) sp[h][jm + t] = p[t];
    __syncwarp();

    // ---- phase 3: PV accumulation ----
    float4 acc = make_float4(0.f, 0.f, 0.f, 0.f);
    for (int j0 = 0; j0 < JPC; j0 += 4) {
#pragma unroll
        for (int u = 0; u < 4; u++) {
            size_t j = (size_t)(jbase + j0 + u);
            float4 vv = *(const float4*)(vp + j * 512);
            float4 cv = *(const float4*)(cvp + j * 131072);
            float pj = sp[h][j0 + u];
            acc.x += pj * (vv.x + cv.x);
            acc.y += pj * (vv.y + cv.y);
            acc.z += pj * (vv.z + cv.z);
            acc.w += pj * (vv.w + cv.w);
        }
    }
    *(float4*)(g_scr4 + ((size_t)(ch * SEQ + bi) << 9) + d0) = acc;
    if (l16 == 0)
        *(float2*)(g_pml + ((size_t)(ch * SEQ + bi) * 8 + h) * 2) = make_float2(m4, l4);
}

// combine 4 chunk partials -> packed split concat planes
__global__ __launch_bounds__(128) void attn_combine_kernel() {
    int bi = blockIdx.x;
    int t = threadIdx.x;
    int d0 = t << 2;
    int h = d0 >> 6;
    float mm[NCH], ll[NCH];
    float M = -INFINITY;
#pragma unroll
    for (int c = 0; c < NCH; c++) {
        float2 ml = *(const float2*)(g_pml + ((size_t)(c * SEQ + bi) * 8 + h) * 2);
        mm[c] = ml.x; ll[c] = ml.y;
        M = fmaxf(M, ml.x);
    }
    float L = 0.f;
    float4 a = make_float4(0.f, 0.f, 0.f, 0.f);
#pragma unroll
    for (int c = 0; c < NCH; c++) {
        float wgt = __expf(mm[c] - M);
        L += ll[c] * wgt;
        float4 p = *(const float4*)(g_scr4 + ((size_t)(c * SEQ + bi) << 9) + d0);
        a.x += p.x * wgt; a.y += p.y * wgt; a.z += p.z * wgt; a.w += p.w * wgt;
    }
    float inv = 1.0f / L;
    float o0 = a.x * inv, o1 = a.y * inv, o2 = a.z * inv, o3 = a.w * inv;
    unsigned s0, s1;
    unsigned b0 = packsplit(o0, o1, s0);
    unsigned b1 = packsplit(o2, o3, s1);
    size_t ow = (size_t)bi * 256 + (d0 >> 1);
    g_ccB[ow] = b0; g_ccB[ow + 1] = b1;
    g_ccS[ow] = s0; g_ccS[ow + 1] = s1;
}

// ---------------- launch ----------------------------------------------------
extern "C" void kernel_launch(void* const* d_in, const int* in_sizes, int n_in,
                              void* d_out, int out_size) {
    const float* x    = (const float*)d_in[0];
    const float* cbk  = (const float*)d_in[1];
    const float* cbv  = (const float*)d_in[2];
    const int*   mask = (const int*)d_in[3];
    const float* Wq = (const float*)d_in[4];
    const float* bq = (const float*)d_in[5];
    const float* Wk = (const float*)d_in[6];
    const float* bk = (const float*)d_in[7];
    const float* Wv = (const float*)d_in[8];
    const float* bv = (const float*)d_in[9];
    const float* Wo = (const float*)d_in[10];
    const float* bo = (const float*)d_in[11];
    const float* alpha1 = (const float*)d_in[12];
    const float* beta1  = (const float*)d_in[13];
    const float* alpha2 = (const float*)d_in[14];
    const float* beta2  = (const float*)d_in[15];
    const float* W1 = (const float*)d_in[16];
    const float* b1 = (const float*)d_in[17];
    const float* W2 = (const float*)d_in[18];
    const float* b2 = (const float*)d_in[19];
    float* out = (float*)d_out;

    unsigned *px2B, *px2S, *pyB, *pyS;
    float *py;
    cudaGetSymbolAddress((void**)&px2B, g_x2B);
    cudaGetSymbolAddress((void**)&px2S, g_x2S);
    cudaGetSymbolAddress((void**)&pyB,  g_y2B);
    cudaGetSymbolAddress((void**)&pyS,  g_y2S);
    cudaGetSymbolAddress((void**)&py,   g_y);

    // 0) split all weights into packed bf16 big/small planes
    split_weights_kernel<<<1536, 256>>>(Wq, Wk, Wv, Wo, W1, W2);
    // 1) LN1 -> packed split x2
    ln_split_kernel<<<512, 256>>>(x, alpha1, beta1, px2B, px2S);
    // 2) fused Q,K,V projections
    gemm_qkv_kernel<<<dim3(8, 16, 3), 128>>>(bq, bk, bv);
    // 3) attention: 4-way split-j 3-phase partials + combine
    attn_part_kernel<<<dim3(512, NCH), 128>>>(cbk, cbv, mask);
    attn_combine_kernel<<<512, 128>>>();
    // 4) output projection + residual(x) -> y
    gemm_wo_kernel<<<dim3(8, 16), 128>>>(bo, x);
    // 5) LN2 -> packed split y2
    ln_split_kernel<<<512, 256>>>(py, alpha2, beta2, pyB, pyS);
    // 6) FFN up + ReLU -> packed split h
    gemm_ffn1_kernel<<<dim3(32, 16), 128>>>(b1);
    // 7) FFN down split-K=4 partials + reduce(+bias+residual) -> out
    gemm_ffn2_part_kernel<<<dim3(8, 16, 4), 128>>>();
    ffn2_reduce_kernel<<<512, 128>>>(b2, out);
}

// round 12
// speedup vs baseline: 3.0899x; 1.0759x over previous
#include <cuda_runtime.h>
#include <cuda_bf16.h>
#include <math.h>

#define SEQ 512   // b*s rows
#define DM  512
#define DF  2048
#define NCH 4     // attention j-chunks
#define JPC 64    // j per chunk

// ---------------- scratch (device globals; no allocation allowed) -----------
__device__ unsigned g_x2B[SEQ*DM/2], g_x2S[SEQ*DM/2];
__device__ float    g_q[SEQ*DM], g_k[SEQ*DM], g_v[SEQ*DM];
__device__ unsigned g_ccB[SEQ*DM/2], g_ccS[SEQ*DM/2];
__device__ float    g_y[SEQ*DM];
__device__ unsigned g_y2B[SEQ*DM/2], g_y2S[SEQ*DM/2];
__device__ unsigned g_hB[SEQ*DF/2], g_hS[SEQ*DF/2];
__device__ float    g_scrA[6*SEQ*DM];     // shared scratch: qkv/wo/ffn2 partials, attn partials
__device__ float    g_pml[NCH*SEQ*8*2];   // attn partial (m,l)
__device__ unsigned g_WqB[DM*DM/2], g_WqS[DM*DM/2];
__device__ unsigned g_WkB[DM*DM/2], g_WkS[DM*DM/2];
__device__ unsigned g_WvB[DM*DM/2], g_WvS[DM*DM/2];
__device__ unsigned g_WoB[DM*DM/2], g_WoS[DM*DM/2];
__device__ unsigned g_W1B[DF*DM/2], g_W1S[DF*DM/2];
__device__ unsigned g_W2B[DM*DF/2], g_W2S[DM*DF/2];

// ---------------- helpers ----------------------------------------------------
__device__ __forceinline__ unsigned packsplit(float x0, float x1, unsigned& small) {
    __nv_bfloat16 b0 = __float2bfloat16_rn(x0);
    __nv_bfloat16 b1 = __float2bfloat16_rn(x1);
    float r0 = x0 - __bfloat162float(b0);
    float r1 = x1 - __bfloat162float(b1);
    __nv_bfloat16 s0 = __float2bfloat16_rn(r0);
    __nv_bfloat16 s1 = __float2bfloat16_rn(r1);
    small = (unsigned)__bfloat16_as_ushort(s0) |
            ((unsigned)__bfloat16_as_ushort(s1) << 16);
    return (unsigned)__bfloat16_as_ushort(b0) |
           ((unsigned)__bfloat16_as_ushort(b1) << 16);
}

__device__ __forceinline__ void mma_bf16(float c[4],
                                         unsigned a0, unsigned a1, unsigned a2, unsigned a3,
                                         unsigned b0, unsigned b1) {
    asm volatile(
        "mma.sync.aligned.m16n8k16.row.col.f32.bf16.bf16.f32 "
        "{%0,%1,%2,%3}, {%4,%5,%6,%7}, {%8,%9}, {%0,%1,%2,%3};"
        : "+f"(c[0]), "+f"(c[1]), "+f"(c[2]), "+f"(c[3])
        : "r"(a0), "r"(a1), "r"(a2), "r"(a3), "r"(b0), "r"(b1));
}

// ---------------- weight splitting -------------------------------------------
__global__ __launch_bounds__(256) void split_weights_kernel(
    const float* __restrict__ Wq, const float* __restrict__ Wk,
    const float* __restrict__ Wv, const float* __restrict__ Wo,
    const float* __restrict__ W1, const float* __restrict__ W2) {
    int i = blockIdx.x * 256 + threadIdx.x;   // float8 index
    const int S8 = 32768, L8 = 131072;
    const float* src; unsigned* dB; unsigned* dS; int o;
    if (i < 4 * S8) {
        int w = i >> 15; o = i & 32767;
        src = (w == 0) ? Wq : (w == 1) ? Wk : (w == 2) ? Wv : Wo;
        dB  = (w == 0) ? g_WqB : (w == 1) ? g_WkB : (w == 2) ? g_WvB : g_WoB;
        dS  = (w == 0) ? g_WqS : (w == 1) ? g_WkS : (w == 2) ? g_WvS : g_WoS;
    } else if (i < 4 * S8 + L8) {
        o = i - 4 * S8; src = W1; dB = g_W1B; dS = g_W1S;
    } else {
        o = i - 4 * S8 - L8; src = W2; dB = g_W2B; dS = g_W2S;
    }
    float4 v0 = ((const float4*)src)[o * 2];
    float4 v1 = ((const float4*)src)[o * 2 + 1];
    uint4 big, sml;
    big.x = packsplit(v0.x, v0.y, sml.x);
    big.y = packsplit(v0.z, v0.w, sml.y);
    big.z = packsplit(v1.x, v1.y, sml.z);
    big.w = packsplit(v1.z, v1.w, sml.w);
    ((uint4*)dB)[o] = big;
    ((uint4*)dS)[o] = sml;
}

// ---------------- LayerNorm (ddof=1) with packed split output ----------------
__global__ __launch_bounds__(256) void ln_split_kernel(
    const float* __restrict__ x, const float* __restrict__ alpha,
    const float* __restrict__ beta, unsigned* __restrict__ outB,
    unsigned* __restrict__ outS) {
    int row = blockIdx.x;
    int t = threadIdx.x;
    float2 v = ((const float2*)(x + (size_t)row * 512))[t];
    float s = v.x + v.y;
    float q = v.x * v.x + v.y * v.y;
    __shared__ float ssum[8], ssq[8];
#pragma unroll
    for (int off = 16; off; off >>= 1) {
        s += __shfl_xor_sync(~0u, s, off);
        q += __shfl_xor_sync(~0u, q, off);
    }
    int w = t >> 5, l = t & 31;
    if (l == 0) { ssum[w] = s; ssq[w] = q; }
    __syncthreads();
    float tot = 0.f, totq = 0.f;
#pragma unroll
    for (int i = 0; i < 8; i++) { tot += ssum[i]; totq += ssq[i]; }
    float mu  = tot * (1.0f / 512.0f);
    float var = (totq - 512.0f * mu * mu) * (1.0f / 511.0f);
    float inv = 1.0f / (sqrtf(var) + 1e-6f);
    float2 a  = ((const float2*)alpha)[t];
    float2 bb = ((const float2*)beta)[t];
    float ox = a.x * (v.x - mu) * inv + bb.x;
    float oy = a.y * (v.y - mu) * inv + bb.y;
    unsigned sm;
    unsigned bg = packsplit(ox, oy, sm);
    outB[row * 256 + t] = bg;
    outS[row * 256 + t] = sm;
}

// ---------------- 3x-split-BF16 GEMM, double-buffered ------------------------
// C tile = A[32 rows] @ B[64 rows]^T, strides in bf16x2 words.
// CTA 32x64, BK = 16 words (32 elems), 128 threads, 1 __syncthreads per stage.
__device__ __forceinline__ void gemm_body(
    const unsigned* __restrict__ AB, const unsigned* __restrict__ AS,
    const unsigned* __restrict__ BB, const unsigned* __restrict__ BS,
    const float* __restrict__ bias, const float* __restrict__ Res,
    float* __restrict__ C, unsigned* __restrict__ CB, unsigned* __restrict__ CS,
    int N, int ldaW, int ldbW, int kWords, int relu) {
    __shared__ unsigned sAB[2][32][20], sAS[2][32][20];
    __shared__ unsigned sBB[2][64][20], sBS[2][64][20];
    int tid = threadIdx.x;
    int m0 = blockIdx.y * 32, n0 = blockIdx.x * 64;
    int ra = tid >> 2, ca = (tid & 3) * 4;
    int rb = tid >> 1, cb = (tid & 1) * 8;
    const unsigned* pAB = AB + (size_t)(m0 + ra) * ldaW + ca;
    const unsigned* pAS = AS + (size_t)(m0 + ra) * ldaW + ca;
    const unsigned* pBB = BB + (size_t)(n0 + rb) * ldbW + cb;
    const unsigned* pBS = BS + (size_t)(n0 + rb) * ldbW + cb;

    int w = tid >> 5, lane = tid & 31;
    int g = lane >> 2, tg = lane & 3;

    float acc[2][2][4] = {};

    uint4 rA_B, rA_S, rB_B[2], rB_S[2];
    rA_B = *(const uint4*)pAB;
    rA_S = *(const uint4*)pAS;
    rB_B[0] = *(const uint4*)pBB; rB_B[1] = *(const uint4*)(pBB + 4);
    rB_S[0] = *(const uint4*)pBS; rB_S[1] = *(const uint4*)(pBS + 4);

    int nst = kWords >> 4;
    for (int st = 0; st < nst; st++) {
        int cur = st & 1;
        // publish stage st (regs -> buf[cur]); buf[cur]'s prior readers finished
        // before the previous stage's barrier.
        *(uint4*)&sAB[cur][ra][ca] = rA_B;
        *(uint4*)&sAS[cur][ra][ca] = rA_S;
        *(uint4*)&sBB[cur][rb][cb] = rB_B[0]; *(uint4*)&sBB[cur][rb][cb + 4] = rB_B[1];
        *(uint4*)&sBS[cur][rb][cb] = rB_S[0]; *(uint4*)&sBS[cur][rb][cb + 4] = rB_S[1];
        __syncthreads();
        if (st + 1 < nst) {   // prefetch stage st+1 (overlaps MMAs below)
            pAB += 16; pAS += 16; pBB += 16; pBS += 16;
            rA_B = *(const uint4*)pAB;
            rA_S = *(const uint4*)pAS;
            rB_B[0] = *(const uint4*)pBB; rB_B[1] = *(const uint4*)(pBB + 4);
            rB_S[0] = *(const uint4*)pBS; rB_S[1] = *(const uint4*)(pBS + 4);
        }
#pragma unroll
        for (int s = 0; s < 16; s += 8) {
            unsigned aB[2][4], aS[2][4], bB[2][2], bS[2][2];
#pragma unroll
            for (int mt = 0; mt < 2; mt++) {
                int r0 = mt * 16 + g;
                aB[mt][0] = sAB[cur][r0][s + tg];
                aB[mt][1] = sAB[cur][r0 + 8][s + tg];
                aB[mt][2] = sAB[cur][r0][s + tg + 4];
                aB[mt][3] = sAB[cur][r0 + 8][s + tg + 4];
                aS[mt][0] = sAS[cur][r0][s + tg];
                aS[mt][1] = sAS[cur][r0 + 8][s + tg];
                aS[mt][2] = sAS[cur][r0][s + tg + 4];
                aS[mt][3] = sAS[cur][r0 + 8][s + tg + 4];
            }
#pragma unroll
            for (int nt = 0; nt < 2; nt++) {
                int c0 = w * 16 + nt * 8 + g;
                bB[nt][0] = sBB[cur][c0][s + tg];
                bB[nt][1] = sBB[cur][c0][s + tg + 4];
                bS[nt][0] = sBS[cur][c0][s + tg];
                bS[nt][1] = sBS[cur][c0][s + tg + 4];
            }
#pragma unroll
            for (int mt = 0; mt < 2; mt++)
#pragma unroll
                for (int nt = 0; nt < 2; nt++) {
                    mma_bf16(acc[mt][nt], aB[mt][0], aB[mt][1], aB[mt][2], aB[mt][3],
                             bB[nt][0], bB[nt][1]);
                    mma_bf16(acc[mt][nt], aB[mt][0], aB[mt][1], aB[mt][2], aB[mt][3],
                             bS[nt][0], bS[nt][1]);
                    mma_bf16(acc[mt][nt], aS[mt][0], aS[mt][1], aS[mt][2], aS[mt][3],
                             bB[nt][0], bB[nt][1]);
                }
        }
    }
    int NW = N >> 1;
#pragma unroll
    for (int mt = 0; mt < 2; mt++)
#pragma unroll
        for (int nt = 0; nt < 2; nt++) {
            int row = m0 + mt * 16 + g;
            int col = n0 + w * 16 + nt * 8 + tg * 2;
            float2 bz = bias ? *(const float2*)(bias + col) : make_float2(0.f, 0.f);
#pragma unroll
            for (int h = 0; h < 2; h++) {
                int rr = row + h * 8;
                float cx = acc[mt][nt][h * 2 + 0] + bz.x;
                float cy = acc[mt][nt][h * 2 + 1] + bz.y;
                if (relu) { cx = fmaxf(cx, 0.f); cy = fmaxf(cy, 0.f); }
                if (Res) {
                    float2 rv = *(const float2*)(Res + (size_t)rr * N + col);
                    cx += rv.x; cy += rv.y;
                }
                if (C)
                    *(float2*)(C + (size_t)rr * N + col) = make_float2(cx, cy);
                if (CB) {
                    unsigned sm;
                    unsigned bg = packsplit(cx, cy, sm);
                    CB[(size_t)rr * NW + (col >> 1)] = bg;
                    CS[(size_t)rr * NW + (col >> 1)] = sm;
                }
            }
        }
}

// QKV split-K=2: z = proj*2 + slice. Partials -> g_scrA[z].
__global__ __launch_bounds__(128) void gemm_qkv_kernel() {
    int z = blockIdx.z;
    int proj = z >> 1, sl = z & 1;
    const unsigned *BB, *BS;
    if (proj == 0)      { BB = g_WqB; BS = g_WqS; }
    else if (proj == 1) { BB = g_WkB; BS = g_WkS; }
    else                { BB = g_WvB; BS = g_WvS; }
    gemm_body(g_x2B + sl * 128, g_x2S + sl * 128, BB + sl * 128, BS + sl * 128,
              nullptr, nullptr, g_scrA + (size_t)z * SEQ * DM, nullptr, nullptr,
              512, 256, 256, 128, 0);
}

__global__ __launch_bounds__(128) void qkv_reduce_kernel(
    const float* __restrict__ bq, const float* __restrict__ bk,
    const float* __restrict__ bv) {
    int idx = blockIdx.x * 128 + threadIdx.x;     // float4 idx, 196608 total
    int proj = idx >> 16;
    int rem = idx & 65535;
    size_t o = (size_t)rem * 4;
    const float* p0 = g_scrA + (size_t)(proj * 2) * SEQ * DM;
    const float* p1 = p0 + SEQ * DM;
    const float* bias = (proj == 0) ? bq : (proj == 1) ? bk : bv;
    float* dst = (proj == 0) ? g_q : (proj == 1) ? g_k : g_v;
    float4 a = *(const float4*)(p0 + o);
    float4 b = *(const float4*)(p1 + o);
    int c4 = (rem & 127) * 4;
    float4 bz = *(const float4*)(bias + c4);
    float4 r;
    r.x = a.x + b.x + bz.x; r.y = a.y + b.y + bz.y;
    r.z = a.z + b.z + bz.z; r.w = a.w + b.w + bz.w;
    *(float4*)(dst + o) = r;
}

// Wo split-K=2: z = slice. Partials -> g_scrA[z].
__global__ __launch_bounds__(128) void gemm_wo_kernel() {
    int sl = blockIdx.z;
    gemm_body(g_ccB + sl * 128, g_ccS + sl * 128, g_WoB + sl * 128, g_WoS + sl * 128,
              nullptr, nullptr, g_scrA + (size_t)sl * SEQ * DM, nullptr, nullptr,
              512, 256, 256, 128, 0);
}

// fused: y = p0+p1+bo+x ; LN2(y) -> packed split y2 ; also store y
__global__ __launch_bounds__(256) void wo_reduce_ln2_kernel(
    const float* __restrict__ bo, const float* __restrict__ x,
    const float* __restrict__ alpha2, const float* __restrict__ beta2) {
    int row = blockIdx.x;
    int t = threadIdx.x;
    size_t o = (size_t)row * 512 + t * 2;
    float2 p0 = *(const float2*)(g_scrA + o);
    float2 p1 = *(const float2*)(g_scrA + SEQ * DM + o);
    float2 bz = *(const float2*)(bo + t * 2);
    float2 xv = *(const float2*)(x + o);
    float vx = p0.x + p1.x + bz.x + xv.x;
    float vy = p0.y + p1.y + bz.y + xv.y;
    *(float2*)(g_y + o) = make_float2(vx, vy);
    float s = vx + vy;
    float q = vx * vx + vy * vy;
    __shared__ float ssum[8], ssq[8];
#pragma unroll
    for (int off = 16; off; off >>= 1) {
        s += __shfl_xor_sync(~0u, s, off);
        q += __shfl_xor_sync(~0u, q, off);
    }
    int w = t >> 5, l = t & 31;
    if (l == 0) { ssum[w] = s; ssq[w] = q; }
    __syncthreads();
    float tot = 0.f, totq = 0.f;
#pragma unroll
    for (int i = 0; i < 8; i++) { tot += ssum[i]; totq += ssq[i]; }
    float mu  = tot * (1.0f / 512.0f);
    float var = (totq - 512.0f * mu * mu) * (1.0f / 511.0f);
    float inv = 1.0f / (sqrtf(var) + 1e-6f);
    float2 a  = ((const float2*)alpha2)[t];
    float2 bb = ((const float2*)beta2)[t];
    float ox = a.x * (vx - mu) * inv + bb.x;
    float oy = a.y * (vy - mu) * inv + bb.y;
    unsigned sm;
    unsigned bg = packsplit(ox, oy, sm);
    g_y2B[row * 256 + t] = bg;
    g_y2S[row * 256 + t] = sm;
}

__global__ __launch_bounds__(128) void gemm_ffn1_kernel(
    const float* __restrict__ b1) {
    gemm_body(g_y2B, g_y2S, g_W1B, g_W1S, b1, nullptr, nullptr, g_hB, g_hS,
              2048, 256, 256, 256, 1);
}

// FFN2 split-K=4
__global__ __launch_bounds__(128) void gemm_ffn2_part_kernel() {
    int s = blockIdx.z;
    gemm_body(g_hB + s * 256, g_hS + s * 256,
              g_W2B + s * 256, g_W2S + s * 256,
              nullptr, nullptr, g_scrA + (size_t)s * SEQ * DM, nullptr, nullptr,
              512, 1024, 1024, 256, 0);
}

__global__ __launch_bounds__(128) void ffn2_reduce_kernel(
    const float* __restrict__ b2, float* __restrict__ out) {
    int idx = blockIdx.x * 128 + threadIdx.x;
    int row = idx >> 7, c4 = (idx & 127) * 4;
    size_t o = (size_t)row * 512 + c4;
    float4 a0 = *(const float4*)(g_scrA + o);
    float4 a1 = *(const float4*)(g_scrA + SEQ * DM + o);
    float4 a2 = *(const float4*)(g_scrA + 2 * SEQ * DM + o);
    float4 a3 = *(const float4*)(g_scrA + (size_t)3 * SEQ * DM + o);
    float4 bz = *(const float4*)(b2 + c4);
    float4 rv = *(const float4*)(g_y + o);
    float4 r;
    r.x = a0.x + a1.x + a2.x + a3.x + bz.x + rv.x;
    r.y = a0.y + a1.y + a2.y + a3.y + bz.y + rv.y;
    r.z = a0.z + a1.z + a2.z + a3.z + bz.z + rv.z;
    r.w = a0.w + a1.w + a2.w + a3.w + bz.w + rv.w;
    *(float4*)(out + o) = r;
}

// ---------------- attention: 3-phase split-j partial pass --------------------
__global__ __launch_bounds__(128, 8) void attn_part_kernel(
    const float* __restrict__ cbk, const float* __restrict__ cbv,
    const int* __restrict__ mask) {
    int bi = blockIdx.x;
    int ch = blockIdx.y;
    int b = bi >> 8, i = bi & 255;
    int tid = threadIdx.x;
    int w = tid >> 5, lane = tid & 31;
    int h = (w << 1) + (lane >> 4);
    int l16 = lane & 15;
    int d0 = (h << 6) + (l16 << 2);

    __shared__ float mb[JPC];
    __shared__ float sp[8][JPC];
    if (tid < JPC)
        mb[tid] = (mask[(b << 8) + ch * JPC + tid] == 1) ? -1e9f : 0.0f;
    __syncthreads();

    const float4 q4 = *(const float4*)(g_q + ((size_t)bi << 9) + d0);
    const float* kp = g_k + (((size_t)b << 8) << 9) + d0;
    const float* vp = g_v + (((size_t)b << 8) << 9) + d0;
    const size_t cb_base = (size_t)b * 33554432 + (size_t)i * 512 + d0;
    const float* ckp = cbk + cb_base;
    const float* cvp = cbv + cb_base;
    int jbase = ch * JPC;

    // ---- phase 1: raw scores (cb stream: evict-first, single-use) ----
    for (int j0 = 0; j0 < JPC; j0 += 4) {
        float s[4];
#pragma unroll
        for (int u = 0; u < 4; u++) {
            size_t j = (size_t)(jbase + j0 + u);
            float4 kk = *(const float4*)(kp + j * 512);
            float4 ck = __ldcs((const float4*)(ckp + j * 131072));
            s[u] = q4.x * kk.x + q4.y * kk.y + q4.z * kk.z + q4.w * kk.w
                 + q4.x * ck.x + q4.y * ck.y + q4.z * ck.z + q4.w * ck.w;
        }
#pragma unroll
        for (int off = 8; off; off >>= 1) {
#pragma unroll
            for (int u = 0; u < 4; u++) s[u] += __shfl_xor_sync(~0u, s[u], off);
        }
        if (l16 == 0) {
#pragma unroll
            for (int u = 0; u < 4; u++) sp[h][j0 + u] = s[u];
        }
    }
    __syncwarp();

    // ---- phase 2: softmax over this chunk ----
    int jm = l16 * 4;
    float sc[4];
#pragma unroll
    for (int t = 0; t < 4; t++)
        sc[t] = sp[h][jm + t] * 0.125f + mb[jm + t];
    float m4 = fmaxf(fmaxf(sc[0], sc[1]), fmaxf(sc[2], sc[3]));
#pragma unroll
    for (int off = 8; off; off >>= 1)
        m4 = fmaxf(m4, __shfl_xor_sync(~0u, m4, off));
    float p[4], l4 = 0.f;
#pragma unroll
    for (int t = 0; t < 4; t++) {
        p[t] = __expf(sc[t] - m4);
        l4 += p[t];
    }
#pragma unroll
    for (int off = 8; off; off >>= 1)
        l4 += __shfl_xor_sync(~0u, l4, off);
#pragma unroll
    for (int t = 0; t < 4; t++) sp[h][jm + t] = p[t];
    __syncwarp();

    // ---- phase 3: PV accumulation ----
    float4 acc = make_float4(0.f, 0.f, 0.f, 0.f);
    for (int j0 = 0; j0 < JPC; j0 += 4) {
#pragma unroll
        for (int u = 0; u < 4; u++) {
            size_t j = (size_t)(jbase + j0 + u);
            float4 vv = *(const float4*)(vp + j * 512);
            float4 cv = __ldcs((const float4*)(cvp + j * 131072));
            float pj = sp[h][j0 + u];
            acc.x += pj * (vv.x + cv.x);
            acc.y += pj * (vv.y + cv.y);
            acc.z += pj * (vv.z + cv.z);
            acc.w += pj * (vv.w + cv.w);
        }
    }
    *(float4*)(g_scrA + ((size_t)(ch * SEQ + bi) << 9) + d0) = acc;
    if (l16 == 0)
        *(float2*)(g_pml + ((size_t)(ch * SEQ + bi) * 8 + h) * 2) = make_float2(m4, l4);
}

// combine 4 chunk partials -> packed split concat planes
__global__ __launch_bounds__(128) void attn_combine_kernel() {
    int bi = blockIdx.x;
    int t = threadIdx.x;
    int d0 = t << 2;
    int h = d0 >> 6;
    float mm[NCH], ll[NCH];
    float M = -INFINITY;
#pragma unroll
    for (int c = 0; c < NCH; c++) {
        float2 ml = *(const float2*)(g_pml + ((size_t)(c * SEQ + bi) * 8 + h) * 2);
        mm[c] = ml.x; ll[c] = ml.y;
        M = fmaxf(M, ml.x);
    }
    float L = 0.f;
    float4 a = make_float4(0.f, 0.f, 0.f, 0.f);
#pragma unroll
    for (int c = 0; c < NCH; c++) {
        float wgt = __expf(mm[c] - M);
        L += ll[c] * wgt;
        float4 p = *(const float4*)(g_scrA + ((size_t)(c * SEQ + bi) << 9) + d0);
        a.x += p.x * wgt; a.y += p.y * wgt; a.z += p.z * wgt; a.w += p.w * wgt;
    }
    float inv = 1.0f / L;
    float o0 = a.x * inv, o1 = a.y * inv, o2 = a.z * inv, o3 = a.w * inv;
    unsigned s0, s1;
    unsigned b0 = packsplit(o0, o1, s0);
    unsigned b1 = packsplit(o2, o3, s1);
    size_t ow = (size_t)bi * 256 + (d0 >> 1);
    g_ccB[ow] = b0; g_ccB[ow + 1] = b1;
    g_ccS[ow] = s0; g_ccS[ow + 1] = s1;
}

// ---------------- launch ----------------------------------------------------
extern "C" void kernel_launch(void* const* d_in, const int* in_sizes, int n_in,
                              void* d_out, int out_size) {
    const float* x    = (const float*)d_in[0];
    const float* cbk  = (const float*)d_in[1];
    const float* cbv  = (const float*)d_in[2];
    const int*   mask = (const int*)d_in[3];
    const float* Wq = (const float*)d_in[4];
    const float* bq = (const float*)d_in[5];
    const float* Wk = (const float*)d_in[6];
    const float* bk = (const float*)d_in[7];
    const float* Wv = (const float*)d_in[8];
    const float* bv = (const float*)d_in[9];
    const float* Wo = (const float*)d_in[10];
    const float* bo = (const float*)d_in[11];
    const float* alpha1 = (const float*)d_in[12];
    const float* beta1  = (const float*)d_in[13];
    const float* alpha2 = (const float*)d_in[14];
    const float* beta2  = (const float*)d_in[15];
    const float* W1 = (const float*)d_in[16];
    const float* b1 = (const float*)d_in[17];
    const float* W2 = (const float*)d_in[18];
    const float* b2 = (const float*)d_in[19];
    float* out = (float*)d_out;

    unsigned *px2B, *px2S;
    cudaGetSymbolAddress((void**)&px2B, g_x2B);
    cudaGetSymbolAddress((void**)&px2S, g_x2S);

    // 0) split all weights into packed bf16 big/small planes
    split_weights_kernel<<<1536, 256>>>(Wq, Wk, Wv, Wo, W1, W2);
    // 1) LN1 -> packed split x2
    ln_split_kernel<<<512, 256>>>(x, alpha1, beta1, px2B, px2S);
    // 2) QKV split-K=2 (768 CTAs) + reduce(+bias)
    gemm_qkv_kernel<<<dim3(8, 16, 6), 128>>>();
    qkv_reduce_kernel<<<1536, 128>>>(bq, bk, bv);
    // 3) attention: 4-way split-j 3-phase partials + combine
    attn_part_kernel<<<dim3(512, NCH), 128>>>(cbk, cbv, mask);
    attn_combine_kernel<<<512, 128>>>();
    // 4) Wo split-K=2 + fused reduce(+bias+residual)+LN2
    gemm_wo_kernel<<<dim3(8, 16, 2), 128>>>();
    wo_reduce_ln2_kernel<<<512, 256>>>(bo, x, alpha2, beta2);
    // 5) FFN up + ReLU -> packed split h
    gemm_ffn1_kernel<<<dim3(32, 16), 128>>>(b1);
    // 6) FFN down split-K=4 + reduce(+bias+residual) -> out
    gemm_ffn2_part_kernel<<<dim3(8, 16, 4), 128>>>();
    ffn2_reduce_kernel<<<512, 128>>>(b2, out);
}